// round 2
// baseline (speedup 1.0000x reference)
#include <cuda_runtime.h>
#include <cuda_bf16.h>
#include <math_constants.h>

// Problem constants
#define BB 4
#define TT 1024
#define CC 1024
#define HH 16
#define DD 64
#define MM (BB*TT)          // 4096 rows
#define FF (4*CC)           // 4096 ffn dim

// ---------------------------------------------------------------------------
// Scratch (device globals; no allocation allowed)
// ---------------------------------------------------------------------------
__device__ float g_h [MM*CC];    // layernorm output
__device__ float g_q [MM*CC];
__device__ float g_k [MM*CC];
__device__ float g_v [MM*CC];
__device__ float g_att[MM*CC];   // attention output [B,T,H,D] == [M,C]
__device__ float g_x1[MM*CC];    // residual stream after self-attn
__device__ float g_x2[MM*CC];    // residual stream after cross-attn
__device__ float g_ff[MM*FF];    // FFN intermediate

// ---------------------------------------------------------------------------
// LayerNorm: one block per row of 1024, 256 threads, float4 per thread
// ---------------------------------------------------------------------------
__global__ __launch_bounds__(256)
void ln_kernel(const float* __restrict__ x, const float* __restrict__ gamma,
               const float* __restrict__ beta, float* __restrict__ out)
{
    __shared__ float red[8];
    const int row = blockIdx.x;
    const int t = threadIdx.x;
    const float4 v = ((const float4*)(x + (size_t)row * CC))[t];

    // mean
    float s = v.x + v.y + v.z + v.w;
    #pragma unroll
    for (int o = 16; o; o >>= 1) s += __shfl_xor_sync(0xffffffffu, s, o);
    if ((t & 31) == 0) red[t >> 5] = s;
    __syncthreads();
    float tot = 0.f;
    #pragma unroll
    for (int i = 0; i < 8; i++) tot += red[i];
    const float mu = tot * (1.0f / CC);
    __syncthreads();  // before reusing red

    // variance
    const float dx = v.x - mu, dy = v.y - mu, dz = v.z - mu, dw = v.w - mu;
    float s2 = dx*dx + dy*dy + dz*dz + dw*dw;
    #pragma unroll
    for (int o = 16; o; o >>= 1) s2 += __shfl_xor_sync(0xffffffffu, s2, o);
    if ((t & 31) == 0) red[t >> 5] = s2;
    __syncthreads();
    float tot2 = 0.f;
    #pragma unroll
    for (int i = 0; i < 8; i++) tot2 += red[i];
    const float inv = rsqrtf(tot2 * (1.0f / CC) + 1e-5f);

    const float4 g4 = ((const float4*)gamma)[t];
    const float4 b4 = ((const float4*)beta)[t];
    float4 o4;
    o4.x = dx * inv * g4.x + b4.x;
    o4.y = dy * inv * g4.y + b4.y;
    o4.z = dz * inv * g4.z + b4.z;
    o4.w = dw * inv * g4.w + b4.w;
    ((float4*)(out + (size_t)row * CC))[t] = o4;
}

// ---------------------------------------------------------------------------
// SGEMM: C[M,N] = A[M,K] @ B[K,N]  (+bias, +relu, +residual)
// 128x128 tile, BK=8, 256 threads, 8x8 per-thread register tile
// M,N multiples of 128; K multiple of 8
// ---------------------------------------------------------------------------
template <bool RELU>
__global__ __launch_bounds__(256)
void sgemm_kernel(const float* __restrict__ A, const float* __restrict__ B,
                  float* __restrict__ C, int M, int N, int K,
                  const float* __restrict__ bias,
                  const float* __restrict__ residual)
{
    constexpr int BM = 128, BN = 128, BK = 8, TM = 8, TN = 8;
    __shared__ float As[BK][BM];  // stored transposed
    __shared__ float Bs[BK][BN];

    const int brow = blockIdx.y, bcol = blockIdx.x;
    const int tid = threadIdx.x;
    const int tcol = tid & 15;       // 0..15
    const int trow = tid >> 4;       // 0..15

    // global load mapping
    const int a_row  = tid >> 1;           // 0..127
    const int a_col4 = (tid & 1) * 4;      // 0 or 4
    const int b_row  = tid >> 5;           // 0..7
    const int b_col4 = (tid & 31) * 4;     // 0..124

    const float* Aptr = A + (size_t)(brow * BM + a_row) * K + a_col4;
    const float* Bptr = B + (size_t)b_row * N + bcol * BN + b_col4;

    float acc[TM][TN];
    #pragma unroll
    for (int i = 0; i < TM; i++)
        #pragma unroll
        for (int j = 0; j < TN; j++) acc[i][j] = 0.f;

    for (int k0 = 0; k0 < K; k0 += BK) {
        const float4 av = *(const float4*)Aptr;
        const float4 bv = *(const float4*)Bptr;
        Aptr += BK;
        Bptr += (size_t)BK * N;
        As[a_col4 + 0][a_row] = av.x;
        As[a_col4 + 1][a_row] = av.y;
        As[a_col4 + 2][a_row] = av.z;
        As[a_col4 + 3][a_row] = av.w;
        *(float4*)&Bs[b_row][b_col4] = bv;
        __syncthreads();

        #pragma unroll
        for (int kk = 0; kk < BK; kk++) {
            float ra[TM], rb[TN];
            #pragma unroll
            for (int i = 0; i < TM; i++) ra[i] = As[kk][trow * TM + i];
            #pragma unroll
            for (int j = 0; j < TN; j++) rb[j] = Bs[kk][tcol * TN + j];
            #pragma unroll
            for (int i = 0; i < TM; i++)
                #pragma unroll
                for (int j = 0; j < TN; j++) acc[i][j] += ra[i] * rb[j];
        }
        __syncthreads();
    }

    const int crow0 = brow * BM + trow * TM;
    const int ccol0 = bcol * BN + tcol * TN;
    #pragma unroll
    for (int i = 0; i < TM; i++) {
        const int r = crow0 + i;
        #pragma unroll
        for (int j = 0; j < TN; j += 4) {
            const int c = ccol0 + j;
            float4 v = make_float4(acc[i][j], acc[i][j+1], acc[i][j+2], acc[i][j+3]);
            if (bias) {
                v.x += bias[c]; v.y += bias[c+1]; v.z += bias[c+2]; v.w += bias[c+3];
            }
            if (RELU) {
                v.x = fmaxf(v.x, 0.f); v.y = fmaxf(v.y, 0.f);
                v.z = fmaxf(v.z, 0.f); v.w = fmaxf(v.w, 0.f);
            }
            if (residual) {
                const float4 rv = *(const float4*)&residual[(size_t)r * N + c];
                v.x += rv.x; v.y += rv.y; v.z += rv.z; v.w += rv.w;
            }
            *(float4*)&C[(size_t)r * N + c] = v;
        }
    }
}

// ---------------------------------------------------------------------------
// Flash attention, fp32. Layout: Q/K/V/O are [B*T, C] with head slice at
// column h*64 (i.e. [B,T,H,D]). 64-query tile per block, 256 threads:
// thread = (qi = tid/4, quad = tid%4); quad owns 16 key-cols / 16 out-dims.
// ---------------------------------------------------------------------------
#define ATT_LDS 68            // padded row stride (floats), keeps float4 align
#define ATT_SMEM_BYTES (4 * 64 * ATT_LDS * (int)sizeof(float))

template <bool CAUSAL>
__global__ __launch_bounds__(256)
void attn_kernel(const float* __restrict__ Q, const float* __restrict__ K,
                 const float* __restrict__ V, float* __restrict__ O)
{
    extern __shared__ float sm[];
    float* Qs = sm;
    float* Ks = Qs + 64 * ATT_LDS;
    float* Vs = Ks + 64 * ATT_LDS;
    float* Ps = Vs + 64 * ATT_LDS;

    const int qt = blockIdx.x, h = blockIdx.y, b = blockIdx.z;
    const int tid  = threadIdx.x;
    const int qi   = tid >> 2;
    const int quad = tid & 3;

    const size_t qbase = ((size_t)b * TT + qt * 64) * CC + h * DD;

    // load Q tile (64 rows x 64 cols)
    {
        const int r = tid >> 2, c0 = (tid & 3) * 16;
        const float4* src = (const float4*)(Q + qbase + (size_t)r * CC + c0);
        float4* dst = (float4*)(Qs + r * ATT_LDS + c0);
        dst[0] = src[0]; dst[1] = src[1]; dst[2] = src[2]; dst[3] = src[3];
    }

    float o[16];
    #pragma unroll
    for (int j = 0; j < 16; j++) o[j] = 0.f;
    float m = -CUDART_INF_F, l = 0.f;

    const int nkt = CAUSAL ? (qt + 1) : (TT / 64);
    const int kj0 = quad * 16;

    for (int kt = 0; kt < nkt; kt++) {
        __syncthreads();   // prior-iteration readers done with Ks/Vs/Ps
        {
            const size_t kbase = ((size_t)b * TT + kt * 64) * CC + h * DD;
            const int r = tid >> 2, c0 = (tid & 3) * 16;
            const float4* ks = (const float4*)(K + kbase + (size_t)r * CC + c0);
            const float4* vs = (const float4*)(V + kbase + (size_t)r * CC + c0);
            float4* kd = (float4*)(Ks + r * ATT_LDS + c0);
            float4* vd = (float4*)(Vs + r * ATT_LDS + c0);
            #pragma unroll
            for (int i = 0; i < 4; i++) { kd[i] = ks[i]; vd[i] = vs[i]; }
        }
        __syncthreads();

        // S = Q @ K^T for this thread's 16 keys
        float s[16];
        #pragma unroll
        for (int j = 0; j < 16; j++) s[j] = 0.f;
        #pragma unroll
        for (int d = 0; d < DD; d += 4) {
            const float4 q4 = *(const float4*)(Qs + qi * ATT_LDS + d);
            #pragma unroll
            for (int j = 0; j < 16; j++) {
                const float4 k4 = *(const float4*)(Ks + (kj0 + j) * ATT_LDS + d);
                s[j] += q4.x*k4.x + q4.y*k4.y + q4.z*k4.z + q4.w*k4.w;
            }
        }

        // scale + causal mask + local max
        float mloc = -CUDART_INF_F;
        #pragma unroll
        for (int j = 0; j < 16; j++) {
            s[j] *= 0.125f;  // 1/sqrt(64)
            if (CAUSAL && kt == qt) {
                if (kj0 + j > qi) s[j] = -CUDART_INF_F;
            }
            mloc = fmaxf(mloc, s[j]);
        }
        mloc = fmaxf(mloc, __shfl_xor_sync(0xffffffffu, mloc, 1));
        mloc = fmaxf(mloc, __shfl_xor_sync(0xffffffffu, mloc, 2));
        const float mnew = fmaxf(m, mloc);
        const float corr = __expf(m - mnew);  // 0 when m == -inf

        float lloc = 0.f;
        #pragma unroll
        for (int j = 0; j < 16; j++) {
            const float p = __expf(s[j] - mnew);
            s[j] = p;
            lloc += p;
        }
        lloc += __shfl_xor_sync(0xffffffffu, lloc, 1);
        lloc += __shfl_xor_sync(0xffffffffu, lloc, 2);
        l = l * corr + lloc;
        m = mnew;
        #pragma unroll
        for (int j = 0; j < 16; j++) o[j] *= corr;

        // publish P row segment (4 lanes of a row are in one warp)
        float* prow = Ps + qi * ATT_LDS + kj0;
        *(float4*)(prow + 0)  = make_float4(s[0],  s[1],  s[2],  s[3]);
        *(float4*)(prow + 4)  = make_float4(s[4],  s[5],  s[6],  s[7]);
        *(float4*)(prow + 8)  = make_float4(s[8],  s[9],  s[10], s[11]);
        *(float4*)(prow + 12) = make_float4(s[12], s[13], s[14], s[15]);
        __syncwarp();

        // O[qi][quad*16 .. +16] += P[qi][:] @ V[:, d-range]
        const int d0 = quad * 16;
        #pragma unroll 8
        for (int kj = 0; kj < 64; kj++) {
            const float p = Ps[qi * ATT_LDS + kj];
            const float* vr = Vs + kj * ATT_LDS + d0;
            const float4 v0 = *(const float4*)(vr + 0);
            const float4 v1 = *(const float4*)(vr + 4);
            const float4 v2 = *(const float4*)(vr + 8);
            const float4 v3 = *(const float4*)(vr + 12);
            o[0]  += p * v0.x; o[1]  += p * v0.y; o[2]  += p * v0.z; o[3]  += p * v0.w;
            o[4]  += p * v1.x; o[5]  += p * v1.y; o[6]  += p * v1.z; o[7]  += p * v1.w;
            o[8]  += p * v2.x; o[9]  += p * v2.y; o[10] += p * v2.z; o[11] += p * v2.w;
            o[12] += p * v3.x; o[13] += p * v3.y; o[14] += p * v3.z; o[15] += p * v3.w;
        }
    }

    const float inv = 1.f / l;
    float* optr = O + qbase + (size_t)qi * CC + quad * 16;
    *(float4*)(optr + 0)  = make_float4(o[0]*inv,  o[1]*inv,  o[2]*inv,  o[3]*inv);
    *(float4*)(optr + 4)  = make_float4(o[4]*inv,  o[5]*inv,  o[6]*inv,  o[7]*inv);
    *(float4*)(optr + 8)  = make_float4(o[8]*inv,  o[9]*inv,  o[10]*inv, o[11]*inv);
    *(float4*)(optr + 12) = make_float4(o[12]*inv, o[13]*inv, o[14]*inv, o[15]*inv);
}

// ---------------------------------------------------------------------------
// Host launcher
// ---------------------------------------------------------------------------
extern "C" void kernel_launch(void* const* d_in, const int* in_sizes, int n_in,
                              void* d_out, int out_size)
{
    (void)in_sizes; (void)n_in; (void)out_size;
    const float* x      = (const float*)d_in[0];
    const float* enc    = (const float*)d_in[1];
    const float* sa_wq  = (const float*)d_in[2];
    const float* sa_wk  = (const float*)d_in[3];
    const float* sa_wv  = (const float*)d_in[4];
    const float* sa_wo  = (const float*)d_in[5];
    const float* sa_bo  = (const float*)d_in[6];
    const float* ca_wq  = (const float*)d_in[7];
    const float* ca_wk  = (const float*)d_in[8];
    const float* ca_wv  = (const float*)d_in[9];
    const float* ca_wo  = (const float*)d_in[10];
    const float* ca_bo  = (const float*)d_in[11];
    const float* ff_w1  = (const float*)d_in[12];
    const float* ff_b1  = (const float*)d_in[13];
    const float* ff_w2  = (const float*)d_in[14];
    const float* ff_b2  = (const float*)d_in[15];
    const float* ln1_g  = (const float*)d_in[16];
    const float* ln1_b  = (const float*)d_in[17];
    const float* ln2_g  = (const float*)d_in[18];
    const float* ln2_b  = (const float*)d_in[19];
    const float* ln3_g  = (const float*)d_in[20];
    const float* ln3_b  = (const float*)d_in[21];
    // d_in[22]=tgt_mask (causal tril, hardcoded), d_in[23]=src_mask (all ones)
    float* out = (float*)d_out;

    float *h, *q, *k, *v, *att, *x1, *x2, *ff;
    cudaGetSymbolAddress((void**)&h,   g_h);
    cudaGetSymbolAddress((void**)&q,   g_q);
    cudaGetSymbolAddress((void**)&k,   g_k);
    cudaGetSymbolAddress((void**)&v,   g_v);
    cudaGetSymbolAddress((void**)&att, g_att);
    cudaGetSymbolAddress((void**)&x1,  g_x1);
    cudaGetSymbolAddress((void**)&x2,  g_x2);
    cudaGetSymbolAddress((void**)&ff,  g_ff);

    cudaFuncSetAttribute(attn_kernel<true>,
                         cudaFuncAttributeMaxDynamicSharedMemorySize, ATT_SMEM_BYTES);
    cudaFuncSetAttribute(attn_kernel<false>,
                         cudaFuncAttributeMaxDynamicSharedMemorySize, ATT_SMEM_BYTES);

    const dim3 gCC(CC / 128, MM / 128);     // (8, 32) for N=1024 GEMMs
    const dim3 gFF(FF / 128, MM / 128);     // (32, 32) for N=4096
    const dim3 gAttn(TT / 64, HH, BB);      // (16, 16, 4)

    // ---- self-attention ----
    ln_kernel<<<MM, 256>>>(x, ln1_g, ln1_b, h);
    sgemm_kernel<false><<<gCC, 256>>>(h, sa_wq, q, MM, CC, CC, nullptr, nullptr);
    sgemm_kernel<false><<<gCC, 256>>>(h, sa_wk, k, MM, CC, CC, nullptr, nullptr);
    sgemm_kernel<false><<<gCC, 256>>>(h, sa_wv, v, MM, CC, CC, nullptr, nullptr);
    attn_kernel<true><<<gAttn, 256, ATT_SMEM_BYTES>>>(q, k, v, att);
    sgemm_kernel<false><<<gCC, 256>>>(att, sa_wo, x1, MM, CC, CC, sa_bo, x);

    // ---- cross-attention ----
    ln_kernel<<<MM, 256>>>(x1, ln2_g, ln2_b, h);
    sgemm_kernel<false><<<gCC, 256>>>(h,   ca_wq, q, MM, CC, CC, nullptr, nullptr);
    sgemm_kernel<false><<<gCC, 256>>>(enc, ca_wk, k, MM, CC, CC, nullptr, nullptr);
    sgemm_kernel<false><<<gCC, 256>>>(enc, ca_wv, v, MM, CC, CC, nullptr, nullptr);
    attn_kernel<false><<<gAttn, 256, ATT_SMEM_BYTES>>>(q, k, v, att);
    sgemm_kernel<false><<<gCC, 256>>>(att, ca_wo, x2, MM, CC, CC, ca_bo, x1);

    // ---- FFN ----
    ln_kernel<<<MM, 256>>>(x2, ln3_g, ln3_b, h);
    sgemm_kernel<true ><<<gFF, 256>>>(h,  ff_w1, ff,  MM, FF, CC, ff_b1, nullptr);
    sgemm_kernel<false><<<gCC, 256>>>(ff, ff_w2, out, MM, CC, FF, ff_b2, x2);
}

// round 3
// speedup vs baseline: 1.7021x; 1.7021x over previous
#include <cuda_runtime.h>
#include <cuda_bf16.h>
#include <math_constants.h>

// Problem constants
#define BB 4
#define TT 1024
#define CC 1024
#define HH 16
#define DD 64
#define MM (BB*TT)          // 4096 rows
#define FF (4*CC)           // 4096 ffn dim

typedef unsigned long long ull;

// ---------------------------------------------------------------------------
// f32x2 packed helpers (Blackwell FFMA2 path — only reachable via PTX)
// ---------------------------------------------------------------------------
__device__ __forceinline__ void fma2(ull& d, ull a, ull b) {
    asm("fma.rn.f32x2 %0, %1, %2, %0;" : "+l"(d) : "l"(a), "l"(b));
}
__device__ __forceinline__ void mul2(ull& d, ull a) {
    asm("mul.rn.f32x2 %0, %0, %1;" : "+l"(d) : "l"(a));
}
__device__ __forceinline__ ull pack2(float x, float y) {
    ull r;
    asm("mov.b64 %0, {%1, %2};" : "=l"(r)
        : "r"(__float_as_uint(x)), "r"(__float_as_uint(y)));
    return r;
}
__device__ __forceinline__ float2 unpack2(ull v) {
    unsigned lo, hi;
    asm("mov.b64 {%0, %1}, %2;" : "=r"(lo), "=r"(hi) : "l"(v));
    return make_float2(__uint_as_float(lo), __uint_as_float(hi));
}

// ---------------------------------------------------------------------------
// Scratch (device globals; no allocation allowed)
// ---------------------------------------------------------------------------
__device__ float g_h [MM*CC];
__device__ float g_q [MM*CC];
__device__ float g_k [MM*CC];
__device__ float g_v [MM*CC];
__device__ float g_att[MM*CC];
__device__ float g_x1[MM*CC];
__device__ float g_x2[MM*CC];
__device__ float g_ff[MM*FF];

// ---------------------------------------------------------------------------
// LayerNorm: one block per row of 1024, 256 threads, float4 per thread
// ---------------------------------------------------------------------------
__global__ __launch_bounds__(256)
void ln_kernel(const float* __restrict__ x, const float* __restrict__ gamma,
               const float* __restrict__ beta, float* __restrict__ out)
{
    __shared__ float red[8];
    const int row = blockIdx.x;
    const int t = threadIdx.x;
    const float4 v = ((const float4*)(x + (size_t)row * CC))[t];

    float s = v.x + v.y + v.z + v.w;
    #pragma unroll
    for (int o = 16; o; o >>= 1) s += __shfl_xor_sync(0xffffffffu, s, o);
    if ((t & 31) == 0) red[t >> 5] = s;
    __syncthreads();
    float tot = 0.f;
    #pragma unroll
    for (int i = 0; i < 8; i++) tot += red[i];
    const float mu = tot * (1.0f / CC);
    __syncthreads();

    const float dx = v.x - mu, dy = v.y - mu, dz = v.z - mu, dw = v.w - mu;
    float s2 = dx*dx + dy*dy + dz*dz + dw*dw;
    #pragma unroll
    for (int o = 16; o; o >>= 1) s2 += __shfl_xor_sync(0xffffffffu, s2, o);
    if ((t & 31) == 0) red[t >> 5] = s2;
    __syncthreads();
    float tot2 = 0.f;
    #pragma unroll
    for (int i = 0; i < 8; i++) tot2 += red[i];
    const float inv = rsqrtf(tot2 * (1.0f / CC) + 1e-5f);

    const float4 g4 = ((const float4*)gamma)[t];
    const float4 b4 = ((const float4*)beta)[t];
    float4 o4;
    o4.x = dx * inv * g4.x + b4.x;
    o4.y = dy * inv * g4.y + b4.y;
    o4.z = dz * inv * g4.z + b4.z;
    o4.w = dw * inv * g4.w + b4.w;
    ((float4*)(out + (size_t)row * CC))[t] = o4;
}

// ---------------------------------------------------------------------------
// SGEMM with packed f32x2 FMA. C[M,N] = A[M,K] @ B[K,N] (+bias,+relu,+residual)
// 128x128 tile, BK=16, 256 threads, 8x8 per-thread tile (as 8x4 f32x2 pairs),
// double-buffered smem. A stored element-duplicated so the pair-broadcast
// operand is a contiguous LDS; B pairs are natural along N.
// ---------------------------------------------------------------------------
#define GEMM_SMEM ((2*16*256 + 2*16*128) * (int)sizeof(float))   // 49152

template <bool RELU>
__global__ __launch_bounds__(256, 2)
void sgemm_kernel(const float* __restrict__ A, const float* __restrict__ B,
                  float* __restrict__ C, int M, int N, int K,
                  const float* __restrict__ bias,
                  const float* __restrict__ residual)
{
    extern __shared__ float sm[];
    float* As2 = sm;                 // [2][16][256]  (dup pairs along M)
    float* Bs  = sm + 2*16*256;      // [2][16][128]

    const int tid = threadIdx.x;
    const int bx = blockIdx.x, by = blockIdx.y;
    const int trow = tid >> 4, tcol = tid & 15;

    const int arow = tid >> 2;            // 0..63
    const int akc  = (tid & 3) * 4;       // k sub-col
    const int brow = tid >> 5;            // 0..7
    const int bnc  = (tid & 31) * 4;      // n sub-col

    const float* Ap0 = A + (size_t)(by*128 + arow) * K + akc;
    const float* Ap1 = Ap0 + (size_t)64 * K;
    const float* Bp0 = B + (size_t)brow * N + bx*128 + bnc;
    const float* Bp1 = Bp0 + (size_t)8 * N;

    ull acc[8][4];
    {
        const ull z = pack2(0.f, 0.f);
        #pragma unroll
        for (int i = 0; i < 8; i++)
            #pragma unroll
            for (int j = 0; j < 4; j++) acc[i][j] = z;
    }

    const int nsteps = K / 16;

    // prologue: tile 0
    {
        const float4 a0 = *(const float4*)Ap0;
        const float4 a1 = *(const float4*)Ap1;
        const float4 b0 = *(const float4*)Bp0;
        const float4 b1 = *(const float4*)Bp1;
        *(float2*)&As2[(akc+0)*256 + 2*arow] = make_float2(a0.x, a0.x);
        *(float2*)&As2[(akc+1)*256 + 2*arow] = make_float2(a0.y, a0.y);
        *(float2*)&As2[(akc+2)*256 + 2*arow] = make_float2(a0.z, a0.z);
        *(float2*)&As2[(akc+3)*256 + 2*arow] = make_float2(a0.w, a0.w);
        *(float2*)&As2[(akc+0)*256 + 2*(arow+64)] = make_float2(a1.x, a1.x);
        *(float2*)&As2[(akc+1)*256 + 2*(arow+64)] = make_float2(a1.y, a1.y);
        *(float2*)&As2[(akc+2)*256 + 2*(arow+64)] = make_float2(a1.z, a1.z);
        *(float2*)&As2[(akc+3)*256 + 2*(arow+64)] = make_float2(a1.w, a1.w);
        *(float4*)&Bs[brow*128 + bnc]     = b0;
        *(float4*)&Bs[(brow+8)*128 + bnc] = b1;
    }
    __syncthreads();

    int cur = 0;
    for (int s = 0; s < nsteps; s++) {
        float4 na0, na1, nb0, nb1;
        const bool more = (s + 1 < nsteps);
        if (more) {
            const int ko = (s + 1) * 16;
            na0 = *(const float4*)(Ap0 + ko);
            na1 = *(const float4*)(Ap1 + ko);
            nb0 = *(const float4*)(Bp0 + (size_t)ko * N);
            nb1 = *(const float4*)(Bp1 + (size_t)ko * N);
        }

        const float* Ab = As2 + cur*(16*256) + trow*16;
        const float* Bb = Bs  + cur*(16*128) + tcol*8;
        #pragma unroll
        for (int kk = 0; kk < 16; kk++) {
            const ulonglong2* pa = (const ulonglong2*)(Ab + kk*256);
            const ulonglong2 A01 = pa[0];
            const ulonglong2 A23 = pa[1];
            const ulonglong2 A45 = pa[2];
            const ulonglong2 A67 = pa[3];
            const ulonglong2* pb = (const ulonglong2*)(Bb + kk*128);
            const ulonglong2 B01 = pb[0];
            const ulonglong2 B23 = pb[1];
            fma2(acc[0][0], A01.x, B01.x); fma2(acc[0][1], A01.x, B01.y);
            fma2(acc[0][2], A01.x, B23.x); fma2(acc[0][3], A01.x, B23.y);
            fma2(acc[1][0], A01.y, B01.x); fma2(acc[1][1], A01.y, B01.y);
            fma2(acc[1][2], A01.y, B23.x); fma2(acc[1][3], A01.y, B23.y);
            fma2(acc[2][0], A23.x, B01.x); fma2(acc[2][1], A23.x, B01.y);
            fma2(acc[2][2], A23.x, B23.x); fma2(acc[2][3], A23.x, B23.y);
            fma2(acc[3][0], A23.y, B01.x); fma2(acc[3][1], A23.y, B01.y);
            fma2(acc[3][2], A23.y, B23.x); fma2(acc[3][3], A23.y, B23.y);
            fma2(acc[4][0], A45.x, B01.x); fma2(acc[4][1], A45.x, B01.y);
            fma2(acc[4][2], A45.x, B23.x); fma2(acc[4][3], A45.x, B23.y);
            fma2(acc[5][0], A45.y, B01.x); fma2(acc[5][1], A45.y, B01.y);
            fma2(acc[5][2], A45.y, B23.x); fma2(acc[5][3], A45.y, B23.y);
            fma2(acc[6][0], A67.x, B01.x); fma2(acc[6][1], A67.x, B01.y);
            fma2(acc[6][2], A67.x, B23.x); fma2(acc[6][3], A67.x, B23.y);
            fma2(acc[7][0], A67.y, B01.x); fma2(acc[7][1], A67.y, B01.y);
            fma2(acc[7][2], A67.y, B23.x); fma2(acc[7][3], A67.y, B23.y);
        }

        if (more) {
            float* Ab2 = As2 + (cur^1)*(16*256);
            float* Bb2 = Bs  + (cur^1)*(16*128);
            *(float2*)&Ab2[(akc+0)*256 + 2*arow] = make_float2(na0.x, na0.x);
            *(float2*)&Ab2[(akc+1)*256 + 2*arow] = make_float2(na0.y, na0.y);
            *(float2*)&Ab2[(akc+2)*256 + 2*arow] = make_float2(na0.z, na0.z);
            *(float2*)&Ab2[(akc+3)*256 + 2*arow] = make_float2(na0.w, na0.w);
            *(float2*)&Ab2[(akc+0)*256 + 2*(arow+64)] = make_float2(na1.x, na1.x);
            *(float2*)&Ab2[(akc+1)*256 + 2*(arow+64)] = make_float2(na1.y, na1.y);
            *(float2*)&Ab2[(akc+2)*256 + 2*(arow+64)] = make_float2(na1.z, na1.z);
            *(float2*)&Ab2[(akc+3)*256 + 2*(arow+64)] = make_float2(na1.w, na1.w);
            *(float4*)&Bb2[brow*128 + bnc]     = nb0;
            *(float4*)&Bb2[(brow+8)*128 + bnc] = nb1;
            __syncthreads();
            cur ^= 1;
        }
    }

    // epilogue: unpack pairs, add bias/relu/residual, store
    float co[8][8];
    #pragma unroll
    for (int i = 0; i < 8; i++)
        #pragma unroll
        for (int j2 = 0; j2 < 4; j2++) {
            const float2 t = unpack2(acc[i][j2]);
            co[i][2*j2]   = t.x;
            co[i][2*j2+1] = t.y;
        }

    const int crow0 = by*128 + trow*8;
    const int ccol0 = bx*128 + tcol*8;
    #pragma unroll
    for (int i = 0; i < 8; i++) {
        const int r = crow0 + i;
        #pragma unroll
        for (int j = 0; j < 8; j += 4) {
            const int c = ccol0 + j;
            float4 v = make_float4(co[i][j], co[i][j+1], co[i][j+2], co[i][j+3]);
            if (bias) {
                v.x += bias[c]; v.y += bias[c+1]; v.z += bias[c+2]; v.w += bias[c+3];
            }
            if (RELU) {
                v.x = fmaxf(v.x, 0.f); v.y = fmaxf(v.y, 0.f);
                v.z = fmaxf(v.z, 0.f); v.w = fmaxf(v.w, 0.f);
            }
            if (residual) {
                const float4 rv = *(const float4*)&residual[(size_t)r * N + c];
                v.x += rv.x; v.y += rv.y; v.z += rv.z; v.w += rv.w;
            }
            *(float4*)&C[(size_t)r * N + c] = v;
        }
    }
}

// ---------------------------------------------------------------------------
// Flash attention fp32, 4x4 micro-tile + f32x2.
// 64-query x 64-key tiles, 256 threads as (tr=tid>>4, tc=tid&15).
// Thread owns queries qr=4*tr..+3; QK keys tc+16j (strided, conflict-friendly);
// PV out-dims dc=4*tc. QK accumulates f32x2 pairs along d (natural pairing);
// P stored transposed [key][query] so PV p-operand is one LDS.128 of 2 pairs.
// ---------------------------------------------------------------------------
#define AL 68
#define ATT_SMEM_BYTES (4 * 64 * AL * (int)sizeof(float))   // 69632

template <bool CAUSAL>
__global__ __launch_bounds__(256)
void attn_kernel(const float* __restrict__ Q, const float* __restrict__ K,
                 const float* __restrict__ V, float* __restrict__ O)
{
    extern __shared__ float sm[];
    float* Qs = sm;
    float* Ks = Qs + 64*AL;
    float* Vs = Ks + 64*AL;
    float* Pt = Vs + 64*AL;   // [key][query]

    const int qt = blockIdx.x, h = blockIdx.y, b = blockIdx.z;
    const int tid = threadIdx.x;
    const int tr = tid >> 4, tc = tid & 15;
    const int qr = tr * 4;
    const int dc = tc * 4;

    const size_t qbase = ((size_t)b*TT + qt*64) * CC + h*DD;

    // load Q tile
    {
        const int r = tid >> 2, c0 = (tid & 3) * 16;
        const float4* src = (const float4*)(Q + qbase + (size_t)r*CC + c0);
        float4* dst = (float4*)(Qs + r*AL + c0);
        dst[0] = src[0]; dst[1] = src[1]; dst[2] = src[2]; dst[3] = src[3];
    }

    ull o2[2][4];
    {
        const ull z = pack2(0.f, 0.f);
        #pragma unroll
        for (int i = 0; i < 2; i++)
            #pragma unroll
            for (int j = 0; j < 4; j++) o2[i][j] = z;
    }
    float m[4], l[4];
    #pragma unroll
    for (int i = 0; i < 4; i++) { m[i] = -CUDART_INF_F; l[i] = 0.f; }

    const int nkt = CAUSAL ? (qt + 1) : (TT / 64);

    for (int kt = 0; kt < nkt; kt++) {
        __syncthreads();   // prior PV done with Vs/Pt; safe to overwrite Ks/Vs
        {
            const size_t kbase = ((size_t)b*TT + kt*64) * CC + h*DD;
            const int r = tid >> 2, c0 = (tid & 3) * 16;
            const float4* ks = (const float4*)(K + kbase + (size_t)r*CC + c0);
            const float4* vs = (const float4*)(V + kbase + (size_t)r*CC + c0);
            float4* kd = (float4*)(Ks + r*AL + c0);
            float4* vd = (float4*)(Vs + r*AL + c0);
            #pragma unroll
            for (int i = 0; i < 4; i++) { kd[i] = ks[i]; vd[i] = vs[i]; }
        }
        __syncthreads();

        // ---- QK: s[i][j] = q_{qr+i} . k_{tc+16j}, pairs over d ----
        ull s2[4][4];
        {
            const ull z = pack2(0.f, 0.f);
            #pragma unroll
            for (int i = 0; i < 4; i++)
                #pragma unroll
                for (int j = 0; j < 4; j++) s2[i][j] = z;
        }
        #pragma unroll
        for (int d = 0; d < DD; d += 4) {
            const ulonglong2 q0 = *(const ulonglong2*)&Qs[(qr+0)*AL + d];
            const ulonglong2 q1 = *(const ulonglong2*)&Qs[(qr+1)*AL + d];
            const ulonglong2 q2 = *(const ulonglong2*)&Qs[(qr+2)*AL + d];
            const ulonglong2 q3 = *(const ulonglong2*)&Qs[(qr+3)*AL + d];
            const ulonglong2 k0 = *(const ulonglong2*)&Ks[(tc +  0)*AL + d];
            const ulonglong2 k1 = *(const ulonglong2*)&Ks[(tc + 16)*AL + d];
            const ulonglong2 k2 = *(const ulonglong2*)&Ks[(tc + 32)*AL + d];
            const ulonglong2 k3 = *(const ulonglong2*)&Ks[(tc + 48)*AL + d];
            fma2(s2[0][0], q0.x, k0.x); fma2(s2[0][0], q0.y, k0.y);
            fma2(s2[0][1], q0.x, k1.x); fma2(s2[0][1], q0.y, k1.y);
            fma2(s2[0][2], q0.x, k2.x); fma2(s2[0][2], q0.y, k2.y);
            fma2(s2[0][3], q0.x, k3.x); fma2(s2[0][3], q0.y, k3.y);
            fma2(s2[1][0], q1.x, k0.x); fma2(s2[1][0], q1.y, k0.y);
            fma2(s2[1][1], q1.x, k1.x); fma2(s2[1][1], q1.y, k1.y);
            fma2(s2[1][2], q1.x, k2.x); fma2(s2[1][2], q1.y, k2.y);
            fma2(s2[1][3], q1.x, k3.x); fma2(s2[1][3], q1.y, k3.y);
            fma2(s2[2][0], q2.x, k0.x); fma2(s2[2][0], q2.y, k0.y);
            fma2(s2[2][1], q2.x, k1.x); fma2(s2[2][1], q2.y, k1.y);
            fma2(s2[2][2], q2.x, k2.x); fma2(s2[2][2], q2.y, k2.y);
            fma2(s2[2][3], q2.x, k3.x); fma2(s2[2][3], q2.y, k3.y);
            fma2(s2[3][0], q3.x, k0.x); fma2(s2[3][0], q3.y, k0.y);
            fma2(s2[3][1], q3.x, k1.x); fma2(s2[3][1], q3.y, k1.y);
            fma2(s2[3][2], q3.x, k2.x); fma2(s2[3][2], q3.y, k2.y);
            fma2(s2[3][3], q3.x, k3.x); fma2(s2[3][3], q3.y, k3.y);
        }

        float s[4][4];
        #pragma unroll
        for (int i = 0; i < 4; i++)
            #pragma unroll
            for (int j = 0; j < 4; j++) {
                const float2 t = unpack2(s2[i][j]);
                s[i][j] = (t.x + t.y) * 0.125f;
            }

        if (CAUSAL && kt == qt) {
            #pragma unroll
            for (int i = 0; i < 4; i++)
                #pragma unroll
                for (int j = 0; j < 4; j++)
                    if (tc + 16*j > qr + i) s[i][j] = -CUDART_INF_F;
        }

        // per-query online softmax update
        float corr[4];
        #pragma unroll
        for (int i = 0; i < 4; i++) {
            float mloc = fmaxf(fmaxf(s[i][0], s[i][1]), fmaxf(s[i][2], s[i][3]));
            #pragma unroll
            for (int o = 8; o; o >>= 1)
                mloc = fmaxf(mloc, __shfl_xor_sync(0xffffffffu, mloc, o));
            const float mn = fmaxf(m[i], mloc);
            corr[i] = __expf(m[i] - mn);
            m[i] = mn;
            float lsum = 0.f;
            #pragma unroll
            for (int j = 0; j < 4; j++) {
                const float p = __expf(s[i][j] - mn);
                s[i][j] = p;
                lsum += p;
            }
            #pragma unroll
            for (int o = 8; o; o >>= 1)
                lsum += __shfl_xor_sync(0xffffffffu, lsum, o);
            l[i] = l[i] * corr[i] + lsum;
        }

        {
            const ull c01 = pack2(corr[0], corr[1]);
            const ull c23 = pack2(corr[2], corr[3]);
            #pragma unroll
            for (int dj = 0; dj < 4; dj++) { mul2(o2[0][dj], c01); mul2(o2[1][dj], c23); }
        }

        // publish P transposed [key][query]
        #pragma unroll
        for (int j = 0; j < 4; j++)
            *(float4*)&Pt[(tc + 16*j)*AL + qr] =
                make_float4(s[0][j], s[1][j], s[2][j], s[3][j]);
        __syncthreads();

        // ---- PV: o2[pair(q)][d] += p2 * dup(v) ----
        #pragma unroll 4
        for (int kj = 0; kj < 64; kj++) {
            const ulonglong2 p2 = *(const ulonglong2*)&Pt[kj*AL + qr];
            const float4 v = *(const float4*)&Vs[kj*AL + dc];
            const ull vx = pack2(v.x, v.x);
            const ull vy = pack2(v.y, v.y);
            const ull vz = pack2(v.z, v.z);
            const ull vw = pack2(v.w, v.w);
            fma2(o2[0][0], p2.x, vx); fma2(o2[0][1], p2.x, vy);
            fma2(o2[0][2], p2.x, vz); fma2(o2[0][3], p2.x, vw);
            fma2(o2[1][0], p2.y, vx); fma2(o2[1][1], p2.y, vy);
            fma2(o2[1][2], p2.y, vz); fma2(o2[1][3], p2.y, vw);
        }
    }

    // finalize
    float inv[4];
    #pragma unroll
    for (int i = 0; i < 4; i++) inv[i] = 1.f / l[i];

    float oo[4][4];
    #pragma unroll
    for (int dj = 0; dj < 4; dj++) {
        const float2 t0 = unpack2(o2[0][dj]);
        const float2 t1 = unpack2(o2[1][dj]);
        oo[0][dj] = t0.x * inv[0];
        oo[1][dj] = t0.y * inv[1];
        oo[2][dj] = t1.x * inv[2];
        oo[3][dj] = t1.y * inv[3];
    }
    #pragma unroll
    for (int i = 0; i < 4; i++) {
        float* optr = O + qbase + (size_t)(qr + i) * CC + dc;
        *(float4*)optr = make_float4(oo[i][0], oo[i][1], oo[i][2], oo[i][3]);
    }
}

// ---------------------------------------------------------------------------
// Host launcher
// ---------------------------------------------------------------------------
extern "C" void kernel_launch(void* const* d_in, const int* in_sizes, int n_in,
                              void* d_out, int out_size)
{
    (void)in_sizes; (void)n_in; (void)out_size;
    const float* x      = (const float*)d_in[0];
    const float* enc    = (const float*)d_in[1];
    const float* sa_wq  = (const float*)d_in[2];
    const float* sa_wk  = (const float*)d_in[3];
    const float* sa_wv  = (const float*)d_in[4];
    const float* sa_wo  = (const float*)d_in[5];
    const float* sa_bo  = (const float*)d_in[6];
    const float* ca_wq  = (const float*)d_in[7];
    const float* ca_wk  = (const float*)d_in[8];
    const float* ca_wv  = (const float*)d_in[9];
    const float* ca_wo  = (const float*)d_in[10];
    const float* ca_bo  = (const float*)d_in[11];
    const float* ff_w1  = (const float*)d_in[12];
    const float* ff_b1  = (const float*)d_in[13];
    const float* ff_w2  = (const float*)d_in[14];
    const float* ff_b2  = (const float*)d_in[15];
    const float* ln1_g  = (const float*)d_in[16];
    const float* ln1_b  = (const float*)d_in[17];
    const float* ln2_g  = (const float*)d_in[18];
    const float* ln2_b  = (const float*)d_in[19];
    const float* ln3_g  = (const float*)d_in[20];
    const float* ln3_b  = (const float*)d_in[21];
    float* out = (float*)d_out;

    float *h, *q, *k, *v, *att, *x1, *x2, *ff;
    cudaGetSymbolAddress((void**)&h,   g_h);
    cudaGetSymbolAddress((void**)&q,   g_q);
    cudaGetSymbolAddress((void**)&k,   g_k);
    cudaGetSymbolAddress((void**)&v,   g_v);
    cudaGetSymbolAddress((void**)&att, g_att);
    cudaGetSymbolAddress((void**)&x1,  g_x1);
    cudaGetSymbolAddress((void**)&x2,  g_x2);
    cudaGetSymbolAddress((void**)&ff,  g_ff);

    cudaFuncSetAttribute(attn_kernel<true>,
                         cudaFuncAttributeMaxDynamicSharedMemorySize, ATT_SMEM_BYTES);
    cudaFuncSetAttribute(attn_kernel<false>,
                         cudaFuncAttributeMaxDynamicSharedMemorySize, ATT_SMEM_BYTES);
    cudaFuncSetAttribute(sgemm_kernel<false>,
                         cudaFuncAttributeMaxDynamicSharedMemorySize, GEMM_SMEM);
    cudaFuncSetAttribute(sgemm_kernel<true>,
                         cudaFuncAttributeMaxDynamicSharedMemorySize, GEMM_SMEM);

    const dim3 gCC(CC / 128, MM / 128);
    const dim3 gFF(FF / 128, MM / 128);
    const dim3 gAttn(TT / 64, HH, BB);

    // ---- self-attention ----
    ln_kernel<<<MM, 256>>>(x, ln1_g, ln1_b, h);
    sgemm_kernel<false><<<gCC, 256, GEMM_SMEM>>>(h, sa_wq, q, MM, CC, CC, nullptr, nullptr);
    sgemm_kernel<false><<<gCC, 256, GEMM_SMEM>>>(h, sa_wk, k, MM, CC, CC, nullptr, nullptr);
    sgemm_kernel<false><<<gCC, 256, GEMM_SMEM>>>(h, sa_wv, v, MM, CC, CC, nullptr, nullptr);
    attn_kernel<true><<<gAttn, 256, ATT_SMEM_BYTES>>>(q, k, v, att);
    sgemm_kernel<false><<<gCC, 256, GEMM_SMEM>>>(att, sa_wo, x1, MM, CC, CC, sa_bo, x);

    // ---- cross-attention ----
    ln_kernel<<<MM, 256>>>(x1, ln2_g, ln2_b, h);
    sgemm_kernel<false><<<gCC, 256, GEMM_SMEM>>>(h,   ca_wq, q, MM, CC, CC, nullptr, nullptr);
    sgemm_kernel<false><<<gCC, 256, GEMM_SMEM>>>(enc, ca_wk, k, MM, CC, CC, nullptr, nullptr);
    sgemm_kernel<false><<<gCC, 256, GEMM_SMEM>>>(enc, ca_wv, v, MM, CC, CC, nullptr, nullptr);
    attn_kernel<false><<<gAttn, 256, ATT_SMEM_BYTES>>>(q, k, v, att);
    sgemm_kernel<false><<<gCC, 256, GEMM_SMEM>>>(att, ca_wo, x2, MM, CC, CC, ca_bo, x1);

    // ---- FFN ----
    ln_kernel<<<MM, 256>>>(x2, ln3_g, ln3_b, h);
    sgemm_kernel<true ><<<gFF, 256, GEMM_SMEM>>>(h,  ff_w1, ff,  MM, FF, CC, ff_b1, nullptr);
    sgemm_kernel<false><<<gCC, 256, GEMM_SMEM>>>(ff, ff_w2, out, MM, CC, FF, ff_b2, x2);
}

// round 4
// speedup vs baseline: 2.4464x; 1.4372x over previous
#include <cuda_runtime.h>
#include <cuda_bf16.h>
#include <math_constants.h>

// Problem constants
#define BB 4
#define TT 1024
#define CC 1024
#define HH 16
#define DD 64
#define MM (BB*TT)          // 4096 rows
#define FF (4*CC)           // 4096 ffn dim

typedef unsigned long long ull;

// ---------------------------------------------------------------------------
// f32x2 packed helpers (Blackwell FFMA2 path — only reachable via PTX)
// ---------------------------------------------------------------------------
__device__ __forceinline__ void fma2(ull& d, ull a, ull b) {
    asm("fma.rn.f32x2 %0, %1, %2, %0;" : "+l"(d) : "l"(a), "l"(b));
}
__device__ __forceinline__ void mul2(ull& d, ull a) {
    asm("mul.rn.f32x2 %0, %0, %1;" : "+l"(d) : "l"(a));
}
__device__ __forceinline__ ull pack2(float x, float y) {
    ull r;
    asm("mov.b64 %0, {%1, %2};" : "=l"(r)
        : "r"(__float_as_uint(x)), "r"(__float_as_uint(y)));
    return r;
}
__device__ __forceinline__ float2 unpack2(ull v) {
    unsigned lo, hi;
    asm("mov.b64 {%0, %1}, %2;" : "=r"(lo), "=r"(hi) : "l"(v));
    return make_float2(__uint_as_float(lo), __uint_as_float(hi));
}

// ---------------------------------------------------------------------------
// Scratch (device globals; no allocation allowed)
// ---------------------------------------------------------------------------
__device__ float g_h [MM*CC];
__device__ float g_q [MM*CC];
__device__ float g_k [MM*CC];
__device__ float g_v [MM*CC];
__device__ float g_att[MM*CC];
__device__ float g_x1[MM*CC];
__device__ float g_x2[MM*CC];
__device__ float g_ff[MM*FF];

// ---------------------------------------------------------------------------
// LayerNorm: one block per row of 1024, 256 threads, float4 per thread
// ---------------------------------------------------------------------------
__global__ __launch_bounds__(256)
void ln_kernel(const float* __restrict__ x, const float* __restrict__ gamma,
               const float* __restrict__ beta, float* __restrict__ out)
{
    __shared__ float red[8];
    const int row = blockIdx.x;
    const int t = threadIdx.x;
    const float4 v = ((const float4*)(x + (size_t)row * CC))[t];

    float s = v.x + v.y + v.z + v.w;
    #pragma unroll
    for (int o = 16; o; o >>= 1) s += __shfl_xor_sync(0xffffffffu, s, o);
    if ((t & 31) == 0) red[t >> 5] = s;
    __syncthreads();
    float tot = 0.f;
    #pragma unroll
    for (int i = 0; i < 8; i++) tot += red[i];
    const float mu = tot * (1.0f / CC);
    __syncthreads();

    const float dx = v.x - mu, dy = v.y - mu, dz = v.z - mu, dw = v.w - mu;
    float s2 = dx*dx + dy*dy + dz*dz + dw*dw;
    #pragma unroll
    for (int o = 16; o; o >>= 1) s2 += __shfl_xor_sync(0xffffffffu, s2, o);
    if ((t & 31) == 0) red[t >> 5] = s2;
    __syncthreads();
    float tot2 = 0.f;
    #pragma unroll
    for (int i = 0; i < 8; i++) tot2 += red[i];
    const float inv = rsqrtf(tot2 * (1.0f / CC) + 1e-5f);

    const float4 g4 = ((const float4*)gamma)[t];
    const float4 b4 = ((const float4*)beta)[t];
    float4 o4;
    o4.x = dx * inv * g4.x + b4.x;
    o4.y = dy * inv * g4.y + b4.y;
    o4.z = dz * inv * g4.z + b4.z;
    o4.w = dw * inv * g4.w + b4.w;
    ((float4*)(out + (size_t)row * CC))[t] = o4;
}

// ---------------------------------------------------------------------------
// SGEMM with packed f32x2 FMA. C[M,N] = A[M,K] @ B[K,N] (+bias,+relu,+residual)
// 128x128 tile, BK=16, 256 threads, double-buffered smem.
// Thread tile: rows {4*trow..+3, +64}, cols {4*tcol..+3, +64} (split blocks).
// A stored PLAIN transposed (no duplication): pair-broadcast operand is built
// in registers via pack2(a,a) (ALU pipe). B pairs are natural along N; all
// smem loads are conflict-free (A broadcast, B 16B lane stride).
// ---------------------------------------------------------------------------
#define GEMM_SMEM ((2*16*128 + 2*16*128) * (int)sizeof(float))   // 32768

template <bool RELU>
__global__ __launch_bounds__(256, 2)
void sgemm_kernel(const float* __restrict__ A, const float* __restrict__ B,
                  float* __restrict__ C, int M, int N, int K,
                  const float* __restrict__ bias,
                  const float* __restrict__ residual)
{
    extern __shared__ float sm[];
    float* As = sm;                  // [2][16][128] transposed, plain
    float* Bs = sm + 2*16*128;       // [2][16][128]

    const int tid = threadIdx.x;
    const int bx = blockIdx.x, by = blockIdx.y;
    const int trow = tid >> 4, tcol = tid & 15;

    const int arow = tid >> 2;            // 0..63
    const int akc  = (tid & 3) * 4;       // k sub-col
    const int brow = tid >> 5;            // 0..7
    const int bnc  = (tid & 31) * 4;      // n sub-col

    const float* Ap0 = A + (size_t)(by*128 + arow) * K + akc;
    const float* Ap1 = Ap0 + (size_t)64 * K;
    const float* Bp0 = B + (size_t)brow * N + bx*128 + bnc;
    const float* Bp1 = Bp0 + (size_t)8 * N;

    ull acc[8][4];
    {
        const ull z = pack2(0.f, 0.f);
        #pragma unroll
        for (int i = 0; i < 8; i++)
            #pragma unroll
            for (int j = 0; j < 4; j++) acc[i][j] = z;
    }

    const int nsteps = K / 16;

    // prologue: tile 0
    {
        const float4 a0 = *(const float4*)Ap0;
        const float4 a1 = *(const float4*)Ap1;
        const float4 b0 = *(const float4*)Bp0;
        const float4 b1 = *(const float4*)Bp1;
        As[(akc+0)*128 + arow] = a0.x;
        As[(akc+1)*128 + arow] = a0.y;
        As[(akc+2)*128 + arow] = a0.z;
        As[(akc+3)*128 + arow] = a0.w;
        As[(akc+0)*128 + arow+64] = a1.x;
        As[(akc+1)*128 + arow+64] = a1.y;
        As[(akc+2)*128 + arow+64] = a1.z;
        As[(akc+3)*128 + arow+64] = a1.w;
        *(float4*)&Bs[brow*128 + bnc]     = b0;
        *(float4*)&Bs[(brow+8)*128 + bnc] = b1;
    }
    __syncthreads();

    int cur = 0;
    for (int s = 0; s < nsteps; s++) {
        float4 na0, na1, nb0, nb1;
        const bool more = (s + 1 < nsteps);
        if (more) {
            const int ko = (s + 1) * 16;
            na0 = *(const float4*)(Ap0 + ko);
            na1 = *(const float4*)(Ap1 + ko);
            nb0 = *(const float4*)(Bp0 + (size_t)ko * N);
            nb1 = *(const float4*)(Bp1 + (size_t)ko * N);
        }

        const float* Ab = As + cur*(16*128) + trow*4;
        const float* Bb = Bs + cur*(16*128) + tcol*4;
        #pragma unroll
        for (int kk = 0; kk < 16; kk++) {
            const float4 alo = *(const float4*)(Ab + kk*128);
            const float4 ahi = *(const float4*)(Ab + kk*128 + 64);
            const ulonglong2 blo = *(const ulonglong2*)(Bb + kk*128);
            const ulonglong2 bhi = *(const ulonglong2*)(Bb + kk*128 + 64);
            const ull a0 = pack2(alo.x, alo.x);
            const ull a1 = pack2(alo.y, alo.y);
            const ull a2 = pack2(alo.z, alo.z);
            const ull a3 = pack2(alo.w, alo.w);
            const ull a4 = pack2(ahi.x, ahi.x);
            const ull a5 = pack2(ahi.y, ahi.y);
            const ull a6 = pack2(ahi.z, ahi.z);
            const ull a7 = pack2(ahi.w, ahi.w);
            fma2(acc[0][0], a0, blo.x); fma2(acc[0][1], a0, blo.y);
            fma2(acc[0][2], a0, bhi.x); fma2(acc[0][3], a0, bhi.y);
            fma2(acc[1][0], a1, blo.x); fma2(acc[1][1], a1, blo.y);
            fma2(acc[1][2], a1, bhi.x); fma2(acc[1][3], a1, bhi.y);
            fma2(acc[2][0], a2, blo.x); fma2(acc[2][1], a2, blo.y);
            fma2(acc[2][2], a2, bhi.x); fma2(acc[2][3], a2, bhi.y);
            fma2(acc[3][0], a3, blo.x); fma2(acc[3][1], a3, blo.y);
            fma2(acc[3][2], a3, bhi.x); fma2(acc[3][3], a3, bhi.y);
            fma2(acc[4][0], a4, blo.x); fma2(acc[4][1], a4, blo.y);
            fma2(acc[4][2], a4, bhi.x); fma2(acc[4][3], a4, bhi.y);
            fma2(acc[5][0], a5, blo.x); fma2(acc[5][1], a5, blo.y);
            fma2(acc[5][2], a5, bhi.x); fma2(acc[5][3], a5, bhi.y);
            fma2(acc[6][0], a6, blo.x); fma2(acc[6][1], a6, blo.y);
            fma2(acc[6][2], a6, bhi.x); fma2(acc[6][3], a6, bhi.y);
            fma2(acc[7][0], a7, blo.x); fma2(acc[7][1], a7, blo.y);
            fma2(acc[7][2], a7, bhi.x); fma2(acc[7][3], a7, bhi.y);
        }

        if (more) {
            float* Ab2 = As + (cur^1)*(16*128);
            float* Bb2 = Bs + (cur^1)*(16*128);
            Ab2[(akc+0)*128 + arow] = na0.x;
            Ab2[(akc+1)*128 + arow] = na0.y;
            Ab2[(akc+2)*128 + arow] = na0.z;
            Ab2[(akc+3)*128 + arow] = na0.w;
            Ab2[(akc+0)*128 + arow+64] = na1.x;
            Ab2[(akc+1)*128 + arow+64] = na1.y;
            Ab2[(akc+2)*128 + arow+64] = na1.z;
            Ab2[(akc+3)*128 + arow+64] = na1.w;
            *(float4*)&Bb2[brow*128 + bnc]     = nb0;
            *(float4*)&Bb2[(brow+8)*128 + bnc] = nb1;
            __syncthreads();
            cur ^= 1;
        }
    }

    // epilogue: rows crow0 + {0..3} and crow0+64+{0..3}; cols ccol0 and ccol0+64
    const int crow0 = by*128 + trow*4;
    const int ccol0 = bx*128 + tcol*4;
    #pragma unroll
    for (int i = 0; i < 8; i++) {
        const int r = crow0 + (i & 3) + (i >> 2) * 64;
        #pragma unroll
        for (int half = 0; half < 2; half++) {
            const int c = ccol0 + half * 64;
            const float2 p0 = unpack2(acc[i][2*half + 0]);
            const float2 p1 = unpack2(acc[i][2*half + 1]);
            float4 v = make_float4(p0.x, p0.y, p1.x, p1.y);
            if (bias) {
                v.x += bias[c]; v.y += bias[c+1]; v.z += bias[c+2]; v.w += bias[c+3];
            }
            if (RELU) {
                v.x = fmaxf(v.x, 0.f); v.y = fmaxf(v.y, 0.f);
                v.z = fmaxf(v.z, 0.f); v.w = fmaxf(v.w, 0.f);
            }
            if (residual) {
                const float4 rv = *(const float4*)&residual[(size_t)r * N + c];
                v.x += rv.x; v.y += rv.y; v.z += rv.z; v.w += rv.w;
            }
            *(float4*)&C[(size_t)r * N + c] = v;
        }
    }
}

// ---------------------------------------------------------------------------
// Flash attention fp32, 4x4 micro-tile + f32x2 (unchanged from R3 — it won).
// ---------------------------------------------------------------------------
#define AL 68
#define ATT_SMEM_BYTES (4 * 64 * AL * (int)sizeof(float))   // 69632

template <bool CAUSAL>
__global__ __launch_bounds__(256)
void attn_kernel(const float* __restrict__ Q, const float* __restrict__ K,
                 const float* __restrict__ V, float* __restrict__ O)
{
    extern __shared__ float sm[];
    float* Qs = sm;
    float* Ks = Qs + 64*AL;
    float* Vs = Ks + 64*AL;
    float* Pt = Vs + 64*AL;   // [key][query]

    const int qt = blockIdx.x, h = blockIdx.y, b = blockIdx.z;
    const int tid = threadIdx.x;
    const int tr = tid >> 4, tc = tid & 15;
    const int qr = tr * 4;
    const int dc = tc * 4;

    const size_t qbase = ((size_t)b*TT + qt*64) * CC + h*DD;

    // load Q tile
    {
        const int r = tid >> 2, c0 = (tid & 3) * 16;
        const float4* src = (const float4*)(Q + qbase + (size_t)r*CC + c0);
        float4* dst = (float4*)(Qs + r*AL + c0);
        dst[0] = src[0]; dst[1] = src[1]; dst[2] = src[2]; dst[3] = src[3];
    }

    ull o2[2][4];
    {
        const ull z = pack2(0.f, 0.f);
        #pragma unroll
        for (int i = 0; i < 2; i++)
            #pragma unroll
            for (int j = 0; j < 4; j++) o2[i][j] = z;
    }
    float m[4], l[4];
    #pragma unroll
    for (int i = 0; i < 4; i++) { m[i] = -CUDART_INF_F; l[i] = 0.f; }

    const int nkt = CAUSAL ? (qt + 1) : (TT / 64);

    for (int kt = 0; kt < nkt; kt++) {
        __syncthreads();
        {
            const size_t kbase = ((size_t)b*TT + kt*64) * CC + h*DD;
            const int r = tid >> 2, c0 = (tid & 3) * 16;
            const float4* ks = (const float4*)(K + kbase + (size_t)r*CC + c0);
            const float4* vs = (const float4*)(V + kbase + (size_t)r*CC + c0);
            float4* kd = (float4*)(Ks + r*AL + c0);
            float4* vd = (float4*)(Vs + r*AL + c0);
            #pragma unroll
            for (int i = 0; i < 4; i++) { kd[i] = ks[i]; vd[i] = vs[i]; }
        }
        __syncthreads();

        // ---- QK: s[i][j] = q_{qr+i} . k_{tc+16j}, pairs over d ----
        ull s2[4][4];
        {
            const ull z = pack2(0.f, 0.f);
            #pragma unroll
            for (int i = 0; i < 4; i++)
                #pragma unroll
                for (int j = 0; j < 4; j++) s2[i][j] = z;
        }
        #pragma unroll
        for (int d = 0; d < DD; d += 4) {
            const ulonglong2 q0 = *(const ulonglong2*)&Qs[(qr+0)*AL + d];
            const ulonglong2 q1 = *(const ulonglong2*)&Qs[(qr+1)*AL + d];
            const ulonglong2 q2 = *(const ulonglong2*)&Qs[(qr+2)*AL + d];
            const ulonglong2 q3 = *(const ulonglong2*)&Qs[(qr+3)*AL + d];
            const ulonglong2 k0 = *(const ulonglong2*)&Ks[(tc +  0)*AL + d];
            const ulonglong2 k1 = *(const ulonglong2*)&Ks[(tc + 16)*AL + d];
            const ulonglong2 k2 = *(const ulonglong2*)&Ks[(tc + 32)*AL + d];
            const ulonglong2 k3 = *(const ulonglong2*)&Ks[(tc + 48)*AL + d];
            fma2(s2[0][0], q0.x, k0.x); fma2(s2[0][0], q0.y, k0.y);
            fma2(s2[0][1], q0.x, k1.x); fma2(s2[0][1], q0.y, k1.y);
            fma2(s2[0][2], q0.x, k2.x); fma2(s2[0][2], q0.y, k2.y);
            fma2(s2[0][3], q0.x, k3.x); fma2(s2[0][3], q0.y, k3.y);
            fma2(s2[1][0], q1.x, k0.x); fma2(s2[1][0], q1.y, k0.y);
            fma2(s2[1][1], q1.x, k1.x); fma2(s2[1][1], q1.y, k1.y);
            fma2(s2[1][2], q1.x, k2.x); fma2(s2[1][2], q1.y, k2.y);
            fma2(s2[1][3], q1.x, k3.x); fma2(s2[1][3], q1.y, k3.y);
            fma2(s2[2][0], q2.x, k0.x); fma2(s2[2][0], q2.y, k0.y);
            fma2(s2[2][1], q2.x, k1.x); fma2(s2[2][1], q2.y, k1.y);
            fma2(s2[2][2], q2.x, k2.x); fma2(s2[2][2], q2.y, k2.y);
            fma2(s2[2][3], q2.x, k3.x); fma2(s2[2][3], q2.y, k3.y);
            fma2(s2[3][0], q3.x, k0.x); fma2(s2[3][0], q3.y, k0.y);
            fma2(s2[3][1], q3.x, k1.x); fma2(s2[3][1], q3.y, k1.y);
            fma2(s2[3][2], q3.x, k2.x); fma2(s2[3][2], q3.y, k2.y);
            fma2(s2[3][3], q3.x, k3.x); fma2(s2[3][3], q3.y, k3.y);
        }

        float s[4][4];
        #pragma unroll
        for (int i = 0; i < 4; i++)
            #pragma unroll
            for (int j = 0; j < 4; j++) {
                const float2 t = unpack2(s2[i][j]);
                s[i][j] = (t.x + t.y) * 0.125f;
            }

        if (CAUSAL && kt == qt) {
            #pragma unroll
            for (int i = 0; i < 4; i++)
                #pragma unroll
                for (int j = 0; j < 4; j++)
                    if (tc + 16*j > qr + i) s[i][j] = -CUDART_INF_F;
        }

        float corr[4];
        #pragma unroll
        for (int i = 0; i < 4; i++) {
            float mloc = fmaxf(fmaxf(s[i][0], s[i][1]), fmaxf(s[i][2], s[i][3]));
            #pragma unroll
            for (int o = 8; o; o >>= 1)
                mloc = fmaxf(mloc, __shfl_xor_sync(0xffffffffu, mloc, o));
            const float mn = fmaxf(m[i], mloc);
            corr[i] = __expf(m[i] - mn);
            m[i] = mn;
            float lsum = 0.f;
            #pragma unroll
            for (int j = 0; j < 4; j++) {
                const float p = __expf(s[i][j] - mn);
                s[i][j] = p;
                lsum += p;
            }
            #pragma unroll
            for (int o = 8; o; o >>= 1)
                lsum += __shfl_xor_sync(0xffffffffu, lsum, o);
            l[i] = l[i] * corr[i] + lsum;
        }

        {
            const ull c01 = pack2(corr[0], corr[1]);
            const ull c23 = pack2(corr[2], corr[3]);
            #pragma unroll
            for (int dj = 0; dj < 4; dj++) { mul2(o2[0][dj], c01); mul2(o2[1][dj], c23); }
        }

        #pragma unroll
        for (int j = 0; j < 4; j++)
            *(float4*)&Pt[(tc + 16*j)*AL + qr] =
                make_float4(s[0][j], s[1][j], s[2][j], s[3][j]);
        __syncwarp();
        __syncthreads();

        #pragma unroll 4
        for (int kj = 0; kj < 64; kj++) {
            const ulonglong2 p2 = *(const ulonglong2*)&Pt[kj*AL + qr];
            const float4 v = *(const float4*)&Vs[kj*AL + dc];
            const ull vx = pack2(v.x, v.x);
            const ull vy = pack2(v.y, v.y);
            const ull vz = pack2(v.z, v.z);
            const ull vw = pack2(v.w, v.w);
            fma2(o2[0][0], p2.x, vx); fma2(o2[0][1], p2.x, vy);
            fma2(o2[0][2], p2.x, vz); fma2(o2[0][3], p2.x, vw);
            fma2(o2[1][0], p2.y, vx); fma2(o2[1][1], p2.y, vy);
            fma2(o2[1][2], p2.y, vz); fma2(o2[1][3], p2.y, vw);
        }
    }

    float inv[4];
    #pragma unroll
    for (int i = 0; i < 4; i++) inv[i] = 1.f / l[i];

    float oo[4][4];
    #pragma unroll
    for (int dj = 0; dj < 4; dj++) {
        const float2 t0 = unpack2(o2[0][dj]);
        const float2 t1 = unpack2(o2[1][dj]);
        oo[0][dj] = t0.x * inv[0];
        oo[1][dj] = t0.y * inv[1];
        oo[2][dj] = t1.x * inv[2];
        oo[3][dj] = t1.y * inv[3];
    }
    #pragma unroll
    for (int i = 0; i < 4; i++) {
        float* optr = O + qbase + (size_t)(qr + i) * CC + dc;
        *(float4*)optr = make_float4(oo[i][0], oo[i][1], oo[i][2], oo[i][3]);
    }
}

// ---------------------------------------------------------------------------
// Host launcher
// ---------------------------------------------------------------------------
extern "C" void kernel_launch(void* const* d_in, const int* in_sizes, int n_in,
                              void* d_out, int out_size)
{
    (void)in_sizes; (void)n_in; (void)out_size;
    const float* x      = (const float*)d_in[0];
    const float* enc    = (const float*)d_in[1];
    const float* sa_wq  = (const float*)d_in[2];
    const float* sa_wk  = (const float*)d_in[3];
    const float* sa_wv  = (const float*)d_in[4];
    const float* sa_wo  = (const float*)d_in[5];
    const float* sa_bo  = (const float*)d_in[6];
    const float* ca_wq  = (const float*)d_in[7];
    const float* ca_wk  = (const float*)d_in[8];
    const float* ca_wv  = (const float*)d_in[9];
    const float* ca_wo  = (const float*)d_in[10];
    const float* ca_bo  = (const float*)d_in[11];
    const float* ff_w1  = (const float*)d_in[12];
    const float* ff_b1  = (const float*)d_in[13];
    const float* ff_w2  = (const float*)d_in[14];
    const float* ff_b2  = (const float*)d_in[15];
    const float* ln1_g  = (const float*)d_in[16];
    const float* ln1_b  = (const float*)d_in[17];
    const float* ln2_g  = (const float*)d_in[18];
    const float* ln2_b  = (const float*)d_in[19];
    const float* ln3_g  = (const float*)d_in[20];
    const float* ln3_b  = (const float*)d_in[21];
    float* out = (float*)d_out;

    float *h, *q, *k, *v, *att, *x1, *x2, *ff;
    cudaGetSymbolAddress((void**)&h,   g_h);
    cudaGetSymbolAddress((void**)&q,   g_q);
    cudaGetSymbolAddress((void**)&k,   g_k);
    cudaGetSymbolAddress((void**)&v,   g_v);
    cudaGetSymbolAddress((void**)&att, g_att);
    cudaGetSymbolAddress((void**)&x1,  g_x1);
    cudaGetSymbolAddress((void**)&x2,  g_x2);
    cudaGetSymbolAddress((void**)&ff,  g_ff);

    cudaFuncSetAttribute(attn_kernel<true>,
                         cudaFuncAttributeMaxDynamicSharedMemorySize, ATT_SMEM_BYTES);
    cudaFuncSetAttribute(attn_kernel<false>,
                         cudaFuncAttributeMaxDynamicSharedMemorySize, ATT_SMEM_BYTES);
    cudaFuncSetAttribute(sgemm_kernel<false>,
                         cudaFuncAttributeMaxDynamicSharedMemorySize, GEMM_SMEM);
    cudaFuncSetAttribute(sgemm_kernel<true>,
                         cudaFuncAttributeMaxDynamicSharedMemorySize, GEMM_SMEM);

    const dim3 gCC(CC / 128, MM / 128);
    const dim3 gFF(FF / 128, MM / 128);
    const dim3 gAttn(TT / 64, HH, BB);

    // ---- self-attention ----
    ln_kernel<<<MM, 256>>>(x, ln1_g, ln1_b, h);
    sgemm_kernel<false><<<gCC, 256, GEMM_SMEM>>>(h, sa_wq, q, MM, CC, CC, nullptr, nullptr);
    sgemm_kernel<false><<<gCC, 256, GEMM_SMEM>>>(h, sa_wk, k, MM, CC, CC, nullptr, nullptr);
    sgemm_kernel<false><<<gCC, 256, GEMM_SMEM>>>(h, sa_wv, v, MM, CC, CC, nullptr, nullptr);
    attn_kernel<true><<<gAttn, 256, ATT_SMEM_BYTES>>>(q, k, v, att);
    sgemm_kernel<false><<<gCC, 256, GEMM_SMEM>>>(att, sa_wo, x1, MM, CC, CC, sa_bo, x);

    // ---- cross-attention ----
    ln_kernel<<<MM, 256>>>(x1, ln2_g, ln2_b, h);
    sgemm_kernel<false><<<gCC, 256, GEMM_SMEM>>>(h,   ca_wq, q, MM, CC, CC, nullptr, nullptr);
    sgemm_kernel<false><<<gCC, 256, GEMM_SMEM>>>(enc, ca_wk, k, MM, CC, CC, nullptr, nullptr);
    sgemm_kernel<false><<<gCC, 256, GEMM_SMEM>>>(enc, ca_wv, v, MM, CC, CC, nullptr, nullptr);
    attn_kernel<false><<<gAttn, 256, ATT_SMEM_BYTES>>>(q, k, v, att);
    sgemm_kernel<false><<<gCC, 256, GEMM_SMEM>>>(att, ca_wo, x2, MM, CC, CC, ca_bo, x1);

    // ---- FFN ----
    ln_kernel<<<MM, 256>>>(x2, ln3_g, ln3_b, h);
    sgemm_kernel<true ><<<gFF, 256, GEMM_SMEM>>>(h,  ff_w1, ff,  MM, FF, CC, ff_b1, nullptr);
    sgemm_kernel<false><<<gCC, 256, GEMM_SMEM>>>(ff, ff_w2, out, MM, CC, FF, ff_b2, x2);
}

// round 8
// speedup vs baseline: 3.3901x; 1.3858x over previous
#include <cuda_runtime.h>
#include <cuda_bf16.h>
#include <math_constants.h>
#include <cstdint>

// Problem constants
#define BB 4
#define TT 1024
#define CC 1024
#define HH 16
#define DD 64
#define MM (BB*TT)          // 4096 rows
#define FF (4*CC)           // 4096 ffn dim

typedef unsigned long long ull;

// ---------------------------------------------------------------------------
// f32x2 packed helpers (attention kernel)
// ---------------------------------------------------------------------------
__device__ __forceinline__ void fma2(ull& d, ull a, ull b) {
    asm("fma.rn.f32x2 %0, %1, %2, %0;" : "+l"(d) : "l"(a), "l"(b));
}
__device__ __forceinline__ void mul2(ull& d, ull a) {
    asm("mul.rn.f32x2 %0, %0, %1;" : "+l"(d) : "l"(a));
}
__device__ __forceinline__ ull pack2(float x, float y) {
    ull r;
    asm("mov.b64 %0, {%1, %2};" : "=l"(r)
        : "r"(__float_as_uint(x)), "r"(__float_as_uint(y)));
    return r;
}
__device__ __forceinline__ float2 unpack2(ull v) {
    unsigned lo, hi;
    asm("mov.b64 {%0, %1}, %2;" : "=r"(lo), "=r"(hi) : "l"(v));
    return make_float2(__uint_as_float(lo), __uint_as_float(hi));
}

// ---------------------------------------------------------------------------
// mma.sync / ldmatrix / cp.async helpers (baseline sm_80+ features)
// ---------------------------------------------------------------------------
__device__ __forceinline__ uint32_t smem_u32(const void* p) {
    uint32_t a;
    asm("{ .reg .u64 t; cvta.to.shared.u64 t, %1; cvt.u32.u64 %0, t; }"
        : "=r"(a) : "l"(p));
    return a;
}
__device__ __forceinline__ void ldsm4(uint32_t* r, uint32_t addr) {
    asm volatile("ldmatrix.sync.aligned.m8n8.x4.shared.b16 {%0,%1,%2,%3}, [%4];"
        : "=r"(r[0]), "=r"(r[1]), "=r"(r[2]), "=r"(r[3]) : "r"(addr));
}
__device__ __forceinline__ void mma16816(float* c, const uint32_t* a, const uint32_t* b) {
    asm volatile(
        "mma.sync.aligned.m16n8k16.row.col.f32.bf16.bf16.f32 "
        "{%0,%1,%2,%3}, {%4,%5,%6,%7}, {%8,%9}, {%0,%1,%2,%3};"
        : "+f"(c[0]), "+f"(c[1]), "+f"(c[2]), "+f"(c[3])
        : "r"(a[0]), "r"(a[1]), "r"(a[2]), "r"(a[3]), "r"(b[0]), "r"(b[1]));
}
__device__ __forceinline__ void cp16(uint32_t dst, const void* src) {
    asm volatile("cp.async.cg.shared.global [%0], [%1], 16;" :: "r"(dst), "l"(src));
}
__device__ __forceinline__ void cp_commit() {
    asm volatile("cp.async.commit_group;");
}
template <int N>
__device__ __forceinline__ void cp_wait() {
    asm volatile("cp.async.wait_group %0;" :: "n"(N));
}

// ---------------------------------------------------------------------------
// bf16 split helpers
// ---------------------------------------------------------------------------
__device__ __forceinline__ void split_pair(float a, float b, unsigned& h, unsigned& l) {
    __nv_bfloat16 ha = __float2bfloat16_rn(a);
    __nv_bfloat16 hb = __float2bfloat16_rn(b);
    __nv_bfloat16 la = __float2bfloat16_rn(a - __bfloat162float(ha));
    __nv_bfloat16 lb = __float2bfloat16_rn(b - __bfloat162float(hb));
    __nv_bfloat162 hp; hp.x = ha; hp.y = hb;
    __nv_bfloat162 lp; lp.x = la; lp.y = lb;
    h = *reinterpret_cast<unsigned*>(&hp);
    l = *reinterpret_cast<unsigned*>(&lp);
}

// ---------------------------------------------------------------------------
// Scratch (device globals)
// ---------------------------------------------------------------------------
__device__ float g_q [MM*CC];
__device__ float g_k [MM*CC];
__device__ float g_v [MM*CC];
__device__ float g_att[MM*CC];
__device__ float g_x1[MM*CC];
__device__ float g_x2[MM*CC];
__device__ __nv_bfloat16 g_ah [MM*CC];
__device__ __nv_bfloat16 g_al [MM*CC];
__device__ __nv_bfloat16 g_ffh[MM*FF];
__device__ __nv_bfloat16 g_ffl[MM*FF];
__device__ __nv_bfloat16 g_wth[CC*FF];
__device__ __nv_bfloat16 g_wtl[CC*FF];

// ---------------------------------------------------------------------------
// LayerNorm emitting bf16 hi/lo split
// ---------------------------------------------------------------------------
__global__ __launch_bounds__(256)
void ln_split_kernel(const float* __restrict__ x, const float* __restrict__ gamma,
                     const float* __restrict__ beta,
                     __nv_bfloat16* __restrict__ oh, __nv_bfloat16* __restrict__ ol)
{
    __shared__ float red[8];
    const int row = blockIdx.x;
    const int t = threadIdx.x;
    const float4 v = ((const float4*)(x + (size_t)row * CC))[t];

    float s = v.x + v.y + v.z + v.w;
    #pragma unroll
    for (int o = 16; o; o >>= 1) s += __shfl_xor_sync(0xffffffffu, s, o);
    if ((t & 31) == 0) red[t >> 5] = s;
    __syncthreads();
    float tot = 0.f;
    #pragma unroll
    for (int i = 0; i < 8; i++) tot += red[i];
    const float mu = tot * (1.0f / CC);
    __syncthreads();

    const float dx = v.x - mu, dy = v.y - mu, dz = v.z - mu, dw = v.w - mu;
    float s2 = dx*dx + dy*dy + dz*dz + dw*dw;
    #pragma unroll
    for (int o = 16; o; o >>= 1) s2 += __shfl_xor_sync(0xffffffffu, s2, o);
    if ((t & 31) == 0) red[t >> 5] = s2;
    __syncthreads();
    float tot2 = 0.f;
    #pragma unroll
    for (int i = 0; i < 8; i++) tot2 += red[i];
    const float inv = rsqrtf(tot2 * (1.0f / CC) + 1e-5f);

    const float4 g4 = ((const float4*)gamma)[t];
    const float4 b4 = ((const float4*)beta)[t];
    const float y0 = dx * inv * g4.x + b4.x;
    const float y1 = dy * inv * g4.y + b4.y;
    const float y2 = dz * inv * g4.z + b4.z;
    const float y3 = dw * inv * g4.w + b4.w;

    uint2 hh, ll;
    split_pair(y0, y1, hh.x, ll.x);
    split_pair(y2, y3, hh.y, ll.y);
    ((uint2*)(oh + (size_t)row * CC))[t] = hh;
    ((uint2*)(ol + (size_t)row * CC))[t] = ll;
}

// ---------------------------------------------------------------------------
// Elementwise fp32 -> bf16 hi/lo
// ---------------------------------------------------------------------------
__global__ __launch_bounds__(256)
void convert_split_kernel(const float* __restrict__ in,
                          __nv_bfloat16* __restrict__ oh,
                          __nv_bfloat16* __restrict__ ol, int n4)
{
    const int i = blockIdx.x * 256 + threadIdx.x;
    if (i >= n4) return;
    const float4 v = ((const float4*)in)[i];
    uint2 hh, ll;
    split_pair(v.x, v.y, hh.x, ll.x);
    split_pair(v.z, v.w, hh.y, ll.y);
    ((uint2*)oh)[i] = hh;
    ((uint2*)ol)[i] = ll;
}

// ---------------------------------------------------------------------------
// Weight transpose + split: W[K,N] fp32 -> Wt_hi/lo[N,K] bf16
// ---------------------------------------------------------------------------
__global__ __launch_bounds__(256)
void wtrans_split_kernel(const float* __restrict__ W,
                         __nv_bfloat16* __restrict__ th,
                         __nv_bfloat16* __restrict__ tl, int K, int N)
{
    __shared__ float tile[32][33];
    const int bx = blockIdx.x;
    const int by = blockIdx.y;
    const int tx = threadIdx.x & 31;
    const int ty = threadIdx.x >> 5;
    #pragma unroll
    for (int i = 0; i < 32; i += 8)
        tile[ty + i][tx] = W[(size_t)(by*32 + ty + i) * N + bx*32 + tx];
    __syncthreads();
    #pragma unroll
    for (int i = 0; i < 32; i += 8) {
        const float v = tile[tx][ty + i];
        const __nv_bfloat16 h = __float2bfloat16_rn(v);
        const __nv_bfloat16 l = __float2bfloat16_rn(v - __bfloat162float(h));
        const size_t o = (size_t)(bx*32 + ty + i) * K + by*32 + tx;
        th[o] = h;
        tl[o] = l;
    }
}

// ---------------------------------------------------------------------------
// HMMA GEMM: D[M,N] = A[M,K] @ Wt[N,K]^T, 3-way bf16 split, fp32 accum.
// 128x128 CTA tile, 8 warps (2 M x 4 N), warp tile 64x32, m16n8k16.
// 3-stage cp.async pipeline. Smem rows padded to 80B (conflict-free ldmatrix).
// ---------------------------------------------------------------------------
#define ROWB 80                            // padded row stride bytes (32 bf16 data)
#define TILE_B (128 * ROWB)                // 10240
#define STAGE_B (4 * TILE_B)               // Ah, Al, Bh, Bl = 40960
#define NSTAGE 3
#define MMA_SMEM (NSTAGE * STAGE_B)        // 122880

template <bool RELU, bool SPLITOUT>
__global__ __launch_bounds__(256, 1)
void mma_gemm_kernel(const __nv_bfloat16* __restrict__ Ah,
                     const __nv_bfloat16* __restrict__ Al,
                     const __nv_bfloat16* __restrict__ Bh,
                     const __nv_bfloat16* __restrict__ Bl,
                     float* __restrict__ C,
                     __nv_bfloat16* __restrict__ Ch,
                     __nv_bfloat16* __restrict__ Cl,
                     int N, int K,
                     const float* __restrict__ bias,
                     const float* __restrict__ residual)
{
    extern __shared__ char dsm[];
    const uint32_t sbase = smem_u32(dsm);

    const int tid = threadIdx.x;
    const int wid = tid >> 5;
    const int lane = tid & 31;
    const int bx = blockIdx.x, by = blockIdx.y;
    const int wm = wid & 1;          // 0..1 (M)
    const int wn = wid >> 1;         // 0..3 (N)

    // global source rows for loading
    const int lrow = tid >> 1;       // 0..127
    const int lh   = tid & 1;        // 0..1 (32B halves of the 64B row chunk)
    const char* srcA_h = (const char*)(Ah + (size_t)(by*128 + lrow) * K);
    const char* srcA_l = (const char*)(Al + (size_t)(by*128 + lrow) * K);
    const char* srcB_h = (const char*)(Bh + (size_t)(bx*128 + lrow) * K);
    const char* srcB_l = (const char*)(Bl + (size_t)(bx*128 + lrow) * K);
    const uint32_t dst_row = lrow * ROWB + lh * 32;

    const int nck = K >> 5;          // 32 bf16 per chunk

    auto load_stage = [&](int stage, int i) {
        const size_t go = (size_t)i * 64 + lh * 32;   // byte offset into row
        const uint32_t d = sbase + stage * STAGE_B + dst_row;
        cp16(d + 0*TILE_B,      srcA_h + go);
        cp16(d + 0*TILE_B + 16, srcA_h + go + 16);
        cp16(d + 1*TILE_B,      srcA_l + go);
        cp16(d + 1*TILE_B + 16, srcA_l + go + 16);
        cp16(d + 2*TILE_B,      srcB_h + go);
        cp16(d + 2*TILE_B + 16, srcB_h + go + 16);
        cp16(d + 3*TILE_B,      srcB_l + go);
        cp16(d + 3*TILE_B + 16, srcB_l + go + 16);
        cp_commit();
    };

    float acc[4][4][4];
    #pragma unroll
    for (int mt = 0; mt < 4; mt++)
        #pragma unroll
        for (int nt = 0; nt < 4; nt++)
            #pragma unroll
            for (int e = 0; e < 4; e++) acc[mt][nt][e] = 0.f;

    load_stage(0, 0);
    load_stage(1, 1);

    // precomputed ldmatrix intra-tile offsets
    const uint32_t aoff = (wm*64 + (lane & 15)) * ROWB + ((lane >> 4) & 1) * 16;
    const uint32_t boff = (wn*32 + (lane & 7) + ((lane >> 4) & 1) * 8) * ROWB
                        + ((lane >> 3) & 1) * 16;

    for (int i = 0; i < nck; i++) {
        const int st = i % NSTAGE;
        cp_wait<1>();
        __syncthreads();

        const uint32_t base = sbase + st * STAGE_B;
        #pragma unroll
        for (int kk = 0; kk < 2; kk++) {           // two k16 per 32-chunk
            const uint32_t kb = kk * 32;           // byte offset of k16
            uint32_t ah[4][4], al[4][4];
            #pragma unroll
            for (int mt = 0; mt < 4; mt++) {
                const uint32_t ao = aoff + mt * 16 * ROWB + kb;
                ldsm4(ah[mt], base + 0*TILE_B + ao);
                ldsm4(al[mt], base + 1*TILE_B + ao);
            }
            uint32_t bh[8], bl[8];                 // 4 n8 tiles x 2 regs
            #pragma unroll
            for (int nt2 = 0; nt2 < 2; nt2++) {
                const uint32_t bo = boff + nt2 * 16 * ROWB + kb;
                ldsm4(bh + nt2*4, base + 2*TILE_B + bo);
                ldsm4(bl + nt2*4, base + 3*TILE_B + bo);
            }
            #pragma unroll
            for (int mt = 0; mt < 4; mt++)
                #pragma unroll
                for (int nt = 0; nt < 4; nt++) {
                    mma16816(acc[mt][nt], ah[mt], bh + nt*2);
                    mma16816(acc[mt][nt], ah[mt], bl + nt*2);
                    mma16816(acc[mt][nt], al[mt], bh + nt*2);
                }
        }

        __syncthreads();
        if (i + 2 < nck) load_stage((i + 2) % NSTAGE, i + 2);
    }

    // ---- epilogue ----
    const int r0 = by*128 + wm*64;
    const int c0 = bx*128 + wn*32;
    #pragma unroll
    for (int mt = 0; mt < 4; mt++) {
        #pragma unroll
        for (int nt = 0; nt < 4; nt++) {
            const int r = r0 + mt*16 + (lane >> 2);
            const int c = c0 + nt*8 + (lane & 3) * 2;
            #pragma unroll
            for (int half = 0; half < 2; half++) {
                const int rr = r + half * 8;
                float v0 = acc[mt][nt][half*2 + 0];
                float v1 = acc[mt][nt][half*2 + 1];
                if (bias) { v0 += bias[c]; v1 += bias[c + 1]; }
                if (RELU) { v0 = fmaxf(v0, 0.f); v1 = fmaxf(v1, 0.f); }
                if (SPLITOUT) {
                    unsigned h, l;
                    split_pair(v0, v1, h, l);
                    *(unsigned*)(Ch + (size_t)rr * N + c) = h;
                    *(unsigned*)(Cl + (size_t)rr * N + c) = l;
                } else {
                    if (residual) {
                        const float2 rv = *(const float2*)&residual[(size_t)rr * N + c];
                        v0 += rv.x; v1 += rv.y;
                    }
                    *(float2*)&C[(size_t)rr * N + c] = make_float2(v0, v1);
                }
            }
        }
    }
}

// ---------------------------------------------------------------------------
// Flash attention fp32, 4x4 micro-tile + f32x2 (unchanged — proven R3/R4).
// ---------------------------------------------------------------------------
#define AL 68
#define ATT_SMEM_BYTES (4 * 64 * AL * (int)sizeof(float))   // 69632

template <bool CAUSAL>
__global__ __launch_bounds__(256)
void attn_kernel(const float* __restrict__ Q, const float* __restrict__ K,
                 const float* __restrict__ V, float* __restrict__ O)
{
    extern __shared__ float sm[];
    float* Qs = sm;
    float* Ks = Qs + 64*AL;
    float* Vs = Ks + 64*AL;
    float* Pt = Vs + 64*AL;   // [key][query]

    const int qt = blockIdx.x, h = blockIdx.y, b = blockIdx.z;
    const int tid = threadIdx.x;
    const int tr = tid >> 4, tc = tid & 15;
    const int qr = tr * 4;
    const int dc = tc * 4;

    const size_t qbase = ((size_t)b*TT + qt*64) * CC + h*DD;

    {
        const int r = tid >> 2, c0 = (tid & 3) * 16;
        const float4* src = (const float4*)(Q + qbase + (size_t)r*CC + c0);
        float4* dst = (float4*)(Qs + r*AL + c0);
        dst[0] = src[0]; dst[1] = src[1]; dst[2] = src[2]; dst[3] = src[3];
    }

    ull o2[2][4];
    {
        const ull z = pack2(0.f, 0.f);
        #pragma unroll
        for (int i = 0; i < 2; i++)
            #pragma unroll
            for (int j = 0; j < 4; j++) o2[i][j] = z;
    }
    float m[4], l[4];
    #pragma unroll
    for (int i = 0; i < 4; i++) { m[i] = -CUDART_INF_F; l[i] = 0.f; }

    const int nkt = CAUSAL ? (qt + 1) : (TT / 64);

    for (int kt = 0; kt < nkt; kt++) {
        __syncthreads();
        {
            const size_t kbase = ((size_t)b*TT + kt*64) * CC + h*DD;
            const int r = tid >> 2, c0 = (tid & 3) * 16;
            const float4* ks = (const float4*)(K + kbase + (size_t)r*CC + c0);
            const float4* vs = (const float4*)(V + kbase + (size_t)r*CC + c0);
            float4* kd = (float4*)(Ks + r*AL + c0);
            float4* vd = (float4*)(Vs + r*AL + c0);
            #pragma unroll
            for (int i = 0; i < 4; i++) { kd[i] = ks[i]; vd[i] = vs[i]; }
        }
        __syncthreads();

        ull s2[4][4];
        {
            const ull z = pack2(0.f, 0.f);
            #pragma unroll
            for (int i = 0; i < 4; i++)
                #pragma unroll
                for (int j = 0; j < 4; j++) s2[i][j] = z;
        }
        #pragma unroll
        for (int d = 0; d < DD; d += 4) {
            const ulonglong2 q0 = *(const ulonglong2*)&Qs[(qr+0)*AL + d];
            const ulonglong2 q1 = *(const ulonglong2*)&Qs[(qr+1)*AL + d];
            const ulonglong2 q2 = *(const ulonglong2*)&Qs[(qr+2)*AL + d];
            const ulonglong2 q3 = *(const ulonglong2*)&Qs[(qr+3)*AL + d];
            const ulonglong2 k0 = *(const ulonglong2*)&Ks[(tc +  0)*AL + d];
            const ulonglong2 k1 = *(const ulonglong2*)&Ks[(tc + 16)*AL + d];
            const ulonglong2 k2 = *(const ulonglong2*)&Ks[(tc + 32)*AL + d];
            const ulonglong2 k3 = *(const ulonglong2*)&Ks[(tc + 48)*AL + d];
            fma2(s2[0][0], q0.x, k0.x); fma2(s2[0][0], q0.y, k0.y);
            fma2(s2[0][1], q0.x, k1.x); fma2(s2[0][1], q0.y, k1.y);
            fma2(s2[0][2], q0.x, k2.x); fma2(s2[0][2], q0.y, k2.y);
            fma2(s2[0][3], q0.x, k3.x); fma2(s2[0][3], q0.y, k3.y);
            fma2(s2[1][0], q1.x, k0.x); fma2(s2[1][0], q1.y, k0.y);
            fma2(s2[1][1], q1.x, k1.x); fma2(s2[1][1], q1.y, k1.y);
            fma2(s2[1][2], q1.x, k2.x); fma2(s2[1][2], q1.y, k2.y);
            fma2(s2[1][3], q1.x, k3.x); fma2(s2[1][3], q1.y, k3.y);
            fma2(s2[2][0], q2.x, k0.x); fma2(s2[2][0], q2.y, k0.y);
            fma2(s2[2][1], q2.x, k1.x); fma2(s2[2][1], q2.y, k1.y);
            fma2(s2[2][2], q2.x, k2.x); fma2(s2[2][2], q2.y, k2.y);
            fma2(s2[2][3], q2.x, k3.x); fma2(s2[2][3], q2.y, k3.y);
            fma2(s2[3][0], q3.x, k0.x); fma2(s2[3][0], q3.y, k0.y);
            fma2(s2[3][1], q3.x, k1.x); fma2(s2[3][1], q3.y, k1.y);
            fma2(s2[3][2], q3.x, k2.x); fma2(s2[3][2], q3.y, k2.y);
            fma2(s2[3][3], q3.x, k3.x); fma2(s2[3][3], q3.y, k3.y);
        }

        float s[4][4];
        #pragma unroll
        for (int i = 0; i < 4; i++)
            #pragma unroll
            for (int j = 0; j < 4; j++) {
                const float2 t = unpack2(s2[i][j]);
                s[i][j] = (t.x + t.y) * 0.125f;
            }

        if (CAUSAL && kt == qt) {
            #pragma unroll
            for (int i = 0; i < 4; i++)
                #pragma unroll
                for (int j = 0; j < 4; j++)
                    if (tc + 16*j > qr + i) s[i][j] = -CUDART_INF_F;
        }

        float corr[4];
        #pragma unroll
        for (int i = 0; i < 4; i++) {
            float mloc = fmaxf(fmaxf(s[i][0], s[i][1]), fmaxf(s[i][2], s[i][3]));
            #pragma unroll
            for (int o = 8; o; o >>= 1)
                mloc = fmaxf(mloc, __shfl_xor_sync(0xffffffffu, mloc, o));
            const float mn = fmaxf(m[i], mloc);
            corr[i] = __expf(m[i] - mn);
            m[i] = mn;
            float lsum = 0.f;
            #pragma unroll
            for (int j = 0; j < 4; j++) {
                const float p = __expf(s[i][j] - mn);
                s[i][j] = p;
                lsum += p;
            }
            #pragma unroll
            for (int o = 8; o; o >>= 1)
                lsum += __shfl_xor_sync(0xffffffffu, lsum, o);
            l[i] = l[i] * corr[i] + lsum;
        }

        {
            const ull c01 = pack2(corr[0], corr[1]);
            const ull c23 = pack2(corr[2], corr[3]);
            #pragma unroll
            for (int dj = 0; dj < 4; dj++) { mul2(o2[0][dj], c01); mul2(o2[1][dj], c23); }
        }

        #pragma unroll
        for (int j = 0; j < 4; j++)
            *(float4*)&Pt[(tc + 16*j)*AL + qr] =
                make_float4(s[0][j], s[1][j], s[2][j], s[3][j]);
        __syncwarp();
        __syncthreads();

        #pragma unroll 4
        for (int kj = 0; kj < 64; kj++) {
            const ulonglong2 p2 = *(const ulonglong2*)&Pt[kj*AL + qr];
            const float4 v = *(const float4*)&Vs[kj*AL + dc];
            const ull vx = pack2(v.x, v.x);
            const ull vy = pack2(v.y, v.y);
            const ull vz = pack2(v.z, v.z);
            const ull vw = pack2(v.w, v.w);
            fma2(o2[0][0], p2.x, vx); fma2(o2[0][1], p2.x, vy);
            fma2(o2[0][2], p2.x, vz); fma2(o2[0][3], p2.x, vw);
            fma2(o2[1][0], p2.y, vx); fma2(o2[1][1], p2.y, vy);
            fma2(o2[1][2], p2.y, vz); fma2(o2[1][3], p2.y, vw);
        }
    }

    float inv[4];
    #pragma unroll
    for (int i = 0; i < 4; i++) inv[i] = 1.f / l[i];

    float oo[4][4];
    #pragma unroll
    for (int dj = 0; dj < 4; dj++) {
        const float2 t0 = unpack2(o2[0][dj]);
        const float2 t1 = unpack2(o2[1][dj]);
        oo[0][dj] = t0.x * inv[0];
        oo[1][dj] = t0.y * inv[1];
        oo[2][dj] = t1.x * inv[2];
        oo[3][dj] = t1.y * inv[3];
    }
    #pragma unroll
    for (int i = 0; i < 4; i++) {
        float* optr = O + qbase + (size_t)(qr + i) * CC + dc;
        *(float4*)optr = make_float4(oo[i][0], oo[i][1], oo[i][2], oo[i][3]);
    }
}

// ---------------------------------------------------------------------------
// Host launcher
// ---------------------------------------------------------------------------
extern "C" void kernel_launch(void* const* d_in, const int* in_sizes, int n_in,
                              void* d_out, int out_size)
{
    (void)in_sizes; (void)n_in; (void)out_size;
    const float* x      = (const float*)d_in[0];
    const float* enc    = (const float*)d_in[1];
    const float* sa_wq  = (const float*)d_in[2];
    const float* sa_wk  = (const float*)d_in[3];
    const float* sa_wv  = (const float*)d_in[4];
    const float* sa_wo  = (const float*)d_in[5];
    const float* sa_bo  = (const float*)d_in[6];
    const float* ca_wq  = (const float*)d_in[7];
    const float* ca_wk  = (const float*)d_in[8];
    const float* ca_wv  = (const float*)d_in[9];
    const float* ca_wo  = (const float*)d_in[10];
    const float* ca_bo  = (const float*)d_in[11];
    const float* ff_w1  = (const float*)d_in[12];
    const float* ff_b1  = (const float*)d_in[13];
    const float* ff_w2  = (const float*)d_in[14];
    const float* ff_b2  = (const float*)d_in[15];
    const float* ln1_g  = (const float*)d_in[16];
    const float* ln1_b  = (const float*)d_in[17];
    const float* ln2_g  = (const float*)d_in[18];
    const float* ln2_b  = (const float*)d_in[19];
    const float* ln3_g  = (const float*)d_in[20];
    const float* ln3_b  = (const float*)d_in[21];
    float* out = (float*)d_out;

    float *q, *k, *v, *att, *x1, *x2;
    __nv_bfloat16 *ah, *al, *ffh, *ffl, *wth, *wtl;
    cudaGetSymbolAddress((void**)&q,   g_q);
    cudaGetSymbolAddress((void**)&k,   g_k);
    cudaGetSymbolAddress((void**)&v,   g_v);
    cudaGetSymbolAddress((void**)&att, g_att);
    cudaGetSymbolAddress((void**)&x1,  g_x1);
    cudaGetSymbolAddress((void**)&x2,  g_x2);
    cudaGetSymbolAddress((void**)&ah,  g_ah);
    cudaGetSymbolAddress((void**)&al,  g_al);
    cudaGetSymbolAddress((void**)&ffh, g_ffh);
    cudaGetSymbolAddress((void**)&ffl, g_ffl);
    cudaGetSymbolAddress((void**)&wth, g_wth);
    cudaGetSymbolAddress((void**)&wtl, g_wtl);

    cudaFuncSetAttribute(attn_kernel<true>,
                         cudaFuncAttributeMaxDynamicSharedMemorySize, ATT_SMEM_BYTES);
    cudaFuncSetAttribute(attn_kernel<false>,
                         cudaFuncAttributeMaxDynamicSharedMemorySize, ATT_SMEM_BYTES);
    cudaFuncSetAttribute(mma_gemm_kernel<false, false>,
                         cudaFuncAttributeMaxDynamicSharedMemorySize, MMA_SMEM);
    cudaFuncSetAttribute(mma_gemm_kernel<true, true>,
                         cudaFuncAttributeMaxDynamicSharedMemorySize, MMA_SMEM);

    const dim3 gCC(CC/128, MM/128);      // (8, 32)
    const dim3 gFF(FF/128, MM/128);      // (32, 32)
    const dim3 gAttn(TT/64, HH, BB);
    const dim3 gT1(CC/32, CC/32);
    const dim3 gT2(FF/32, CC/32);
    const dim3 gT3(CC/32, FF/32);
    const int cvt_blocks = (MM*CC/4 + 255) / 256;

    #define GEMM(AH, AL_, N_, K_, BIAS, RES, OUT) \
        mma_gemm_kernel<false,false><<<dim3((N_)/128, MM/128), 256, MMA_SMEM>>>( \
            AH, AL_, wth, wtl, OUT, nullptr, nullptr, N_, K_, BIAS, RES)

    // ---- self-attention ----
    ln_split_kernel<<<MM, 256>>>(x, ln1_g, ln1_b, ah, al);
    wtrans_split_kernel<<<gT1, 256>>>(sa_wq, wth, wtl, CC, CC);
    GEMM(ah, al, CC, CC, nullptr, nullptr, q);
    wtrans_split_kernel<<<gT1, 256>>>(sa_wk, wth, wtl, CC, CC);
    GEMM(ah, al, CC, CC, nullptr, nullptr, k);
    wtrans_split_kernel<<<gT1, 256>>>(sa_wv, wth, wtl, CC, CC);
    GEMM(ah, al, CC, CC, nullptr, nullptr, v);
    attn_kernel<true><<<gAttn, 256, ATT_SMEM_BYTES>>>(q, k, v, att);
    convert_split_kernel<<<cvt_blocks, 256>>>(att, ah, al, MM*CC/4);
    wtrans_split_kernel<<<gT1, 256>>>(sa_wo, wth, wtl, CC, CC);
    GEMM(ah, al, CC, CC, sa_bo, x, x1);

    // ---- cross-attention ----
    ln_split_kernel<<<MM, 256>>>(x1, ln2_g, ln2_b, ah, al);
    wtrans_split_kernel<<<gT1, 256>>>(ca_wq, wth, wtl, CC, CC);
    GEMM(ah, al, CC, CC, nullptr, nullptr, q);
    convert_split_kernel<<<cvt_blocks, 256>>>(enc, ah, al, MM*CC/4);
    wtrans_split_kernel<<<gT1, 256>>>(ca_wk, wth, wtl, CC, CC);
    GEMM(ah, al, CC, CC, nullptr, nullptr, k);
    wtrans_split_kernel<<<gT1, 256>>>(ca_wv, wth, wtl, CC, CC);
    GEMM(ah, al, CC, CC, nullptr, nullptr, v);
    attn_kernel<false><<<gAttn, 256, ATT_SMEM_BYTES>>>(q, k, v, att);
    convert_split_kernel<<<cvt_blocks, 256>>>(att, ah, al, MM*CC/4);
    wtrans_split_kernel<<<gT1, 256>>>(ca_wo, wth, wtl, CC, CC);
    GEMM(ah, al, CC, CC, ca_bo, x1, x2);

    // ---- FFN ----
    ln_split_kernel<<<MM, 256>>>(x2, ln3_g, ln3_b, ah, al);
    wtrans_split_kernel<<<gT2, 256>>>(ff_w1, wth, wtl, CC, FF);
    mma_gemm_kernel<true, true><<<gFF, 256, MMA_SMEM>>>(
        ah, al, wth, wtl, nullptr, ffh, ffl, FF, CC, ff_b1, nullptr);
    wtrans_split_kernel<<<gT3, 256>>>(ff_w2, wth, wtl, FF, CC);
    mma_gemm_kernel<false, false><<<gCC, 256, MMA_SMEM>>>(
        ffh, ffl, wth, wtl, out, nullptr, nullptr, CC, FF, ff_b2, x2);

    #undef GEMM
}

// round 9
// speedup vs baseline: 3.7396x; 1.1031x over previous
#include <cuda_runtime.h>
#include <cuda_bf16.h>
#include <math_constants.h>
#include <cstdint>

// Problem constants
#define BB 4
#define TT 1024
#define CC 1024
#define HH 16
#define DD 64
#define MM (BB*TT)          // 4096 rows
#define FF (4*CC)           // 4096 ffn dim

typedef unsigned long long ull;

// ---------------------------------------------------------------------------
// f32x2 packed helpers (attention kernel)
// ---------------------------------------------------------------------------
__device__ __forceinline__ void fma2(ull& d, ull a, ull b) {
    asm("fma.rn.f32x2 %0, %1, %2, %0;" : "+l"(d) : "l"(a), "l"(b));
}
__device__ __forceinline__ void mul2(ull& d, ull a) {
    asm("mul.rn.f32x2 %0, %0, %1;" : "+l"(d) : "l"(a));
}
__device__ __forceinline__ ull pack2(float x, float y) {
    ull r;
    asm("mov.b64 %0, {%1, %2};" : "=l"(r)
        : "r"(__float_as_uint(x)), "r"(__float_as_uint(y)));
    return r;
}
__device__ __forceinline__ float2 unpack2(ull v) {
    unsigned lo, hi;
    asm("mov.b64 {%0, %1}, %2;" : "=r"(lo), "=r"(hi) : "l"(v));
    return make_float2(__uint_as_float(lo), __uint_as_float(hi));
}

// ---------------------------------------------------------------------------
// mma.sync / ldmatrix / cp.async helpers (baseline sm_80+ features)
// ---------------------------------------------------------------------------
__device__ __forceinline__ uint32_t smem_u32(const void* p) {
    uint32_t a;
    asm("{ .reg .u64 t; cvta.to.shared.u64 t, %1; cvt.u32.u64 %0, t; }"
        : "=r"(a) : "l"(p));
    return a;
}
__device__ __forceinline__ void ldsm4(uint32_t* r, uint32_t addr) {
    asm volatile("ldmatrix.sync.aligned.m8n8.x4.shared.b16 {%0,%1,%2,%3}, [%4];"
        : "=r"(r[0]), "=r"(r[1]), "=r"(r[2]), "=r"(r[3]) : "r"(addr));
}
__device__ __forceinline__ void mma16816(float* c, const uint32_t* a, const uint32_t* b) {
    asm volatile(
        "mma.sync.aligned.m16n8k16.row.col.f32.bf16.bf16.f32 "
        "{%0,%1,%2,%3}, {%4,%5,%6,%7}, {%8,%9}, {%0,%1,%2,%3};"
        : "+f"(c[0]), "+f"(c[1]), "+f"(c[2]), "+f"(c[3])
        : "r"(a[0]), "r"(a[1]), "r"(a[2]), "r"(a[3]), "r"(b[0]), "r"(b[1]));
}
__device__ __forceinline__ void cp16(uint32_t dst, const void* src) {
    asm volatile("cp.async.cg.shared.global [%0], [%1], 16;" :: "r"(dst), "l"(src));
}
__device__ __forceinline__ void cp_commit() {
    asm volatile("cp.async.commit_group;");
}
template <int N>
__device__ __forceinline__ void cp_wait() {
    asm volatile("cp.async.wait_group %0;" :: "n"(N));
}

// ---------------------------------------------------------------------------
// bf16 split helpers
// ---------------------------------------------------------------------------
__device__ __forceinline__ void split_pair(float a, float b, unsigned& h, unsigned& l) {
    __nv_bfloat16 ha = __float2bfloat16_rn(a);
    __nv_bfloat16 hb = __float2bfloat16_rn(b);
    __nv_bfloat16 la = __float2bfloat16_rn(a - __bfloat162float(ha));
    __nv_bfloat16 lb = __float2bfloat16_rn(b - __bfloat162float(hb));
    __nv_bfloat162 hp; hp.x = ha; hp.y = hb;
    __nv_bfloat162 lp; lp.x = la; lp.y = lb;
    h = *reinterpret_cast<unsigned*>(&hp);
    l = *reinterpret_cast<unsigned*>(&lp);
}

// ---------------------------------------------------------------------------
// Scratch (device globals)
// ---------------------------------------------------------------------------
__device__ float g_q [MM*CC];
__device__ float g_k [MM*CC];
__device__ float g_v [MM*CC];
__device__ float g_x1[MM*CC];
__device__ float g_x2[MM*CC];
__device__ __nv_bfloat16 g_ah [MM*CC];
__device__ __nv_bfloat16 g_al [MM*CC];
__device__ __nv_bfloat16 g_ffh[MM*FF];
__device__ __nv_bfloat16 g_ffl[MM*FF];
__device__ __nv_bfloat16 g_wth[CC*FF];
__device__ __nv_bfloat16 g_wtl[CC*FF];

// ---------------------------------------------------------------------------
// LayerNorm emitting bf16 hi/lo split
// ---------------------------------------------------------------------------
__global__ __launch_bounds__(256)
void ln_split_kernel(const float* __restrict__ x, const float* __restrict__ gamma,
                     const float* __restrict__ beta,
                     __nv_bfloat16* __restrict__ oh, __nv_bfloat16* __restrict__ ol)
{
    __shared__ float red[8];
    const int row = blockIdx.x;
    const int t = threadIdx.x;
    const float4 v = ((const float4*)(x + (size_t)row * CC))[t];

    float s = v.x + v.y + v.z + v.w;
    #pragma unroll
    for (int o = 16; o; o >>= 1) s += __shfl_xor_sync(0xffffffffu, s, o);
    if ((t & 31) == 0) red[t >> 5] = s;
    __syncthreads();
    float tot = 0.f;
    #pragma unroll
    for (int i = 0; i < 8; i++) tot += red[i];
    const float mu = tot * (1.0f / CC);
    __syncthreads();

    const float dx = v.x - mu, dy = v.y - mu, dz = v.z - mu, dw = v.w - mu;
    float s2 = dx*dx + dy*dy + dz*dz + dw*dw;
    #pragma unroll
    for (int o = 16; o; o >>= 1) s2 += __shfl_xor_sync(0xffffffffu, s2, o);
    if ((t & 31) == 0) red[t >> 5] = s2;
    __syncthreads();
    float tot2 = 0.f;
    #pragma unroll
    for (int i = 0; i < 8; i++) tot2 += red[i];
    const float inv = rsqrtf(tot2 * (1.0f / CC) + 1e-5f);

    const float4 g4 = ((const float4*)gamma)[t];
    const float4 b4 = ((const float4*)beta)[t];
    const float y0 = dx * inv * g4.x + b4.x;
    const float y1 = dy * inv * g4.y + b4.y;
    const float y2 = dz * inv * g4.z + b4.z;
    const float y3 = dw * inv * g4.w + b4.w;

    uint2 hh, ll;
    split_pair(y0, y1, hh.x, ll.x);
    split_pair(y2, y3, hh.y, ll.y);
    ((uint2*)(oh + (size_t)row * CC))[t] = hh;
    ((uint2*)(ol + (size_t)row * CC))[t] = ll;
}

// ---------------------------------------------------------------------------
// Elementwise fp32 -> bf16 hi/lo (for enc)
// ---------------------------------------------------------------------------
__global__ __launch_bounds__(256)
void convert_split_kernel(const float* __restrict__ in,
                          __nv_bfloat16* __restrict__ oh,
                          __nv_bfloat16* __restrict__ ol, int n4)
{
    const int i = blockIdx.x * 256 + threadIdx.x;
    if (i >= n4) return;
    const float4 v = ((const float4*)in)[i];
    uint2 hh, ll;
    split_pair(v.x, v.y, hh.x, ll.x);
    split_pair(v.z, v.w, hh.y, ll.y);
    ((uint2*)oh)[i] = hh;
    ((uint2*)ol)[i] = ll;
}

// ---------------------------------------------------------------------------
// Weight transpose + split: W[K,N] fp32 -> Wt_hi/lo[N,K] bf16
// ---------------------------------------------------------------------------
__global__ __launch_bounds__(256)
void wtrans_split_kernel(const float* __restrict__ W,
                         __nv_bfloat16* __restrict__ th,
                         __nv_bfloat16* __restrict__ tl, int K, int N)
{
    __shared__ float tile[32][33];
    const int bx = blockIdx.x;
    const int by = blockIdx.y;
    const int tx = threadIdx.x & 31;
    const int ty = threadIdx.x >> 5;
    #pragma unroll
    for (int i = 0; i < 32; i += 8)
        tile[ty + i][tx] = W[(size_t)(by*32 + ty + i) * N + bx*32 + tx];
    __syncthreads();
    #pragma unroll
    for (int i = 0; i < 32; i += 8) {
        const float v = tile[tx][ty + i];
        const __nv_bfloat16 h = __float2bfloat16_rn(v);
        const __nv_bfloat16 l = __float2bfloat16_rn(v - __bfloat162float(h));
        const size_t o = (size_t)(bx*32 + ty + i) * K + by*32 + tx;
        th[o] = h;
        tl[o] = l;
    }
}

// ---------------------------------------------------------------------------
// HMMA GEMM: D[M,N] = A[M,K] @ Wt[N,K]^T, 3-way bf16 split, fp32 accum.
// 128x128 CTA tile, 8 warps (2 M x 4 N), warp tile 64x32, m16n8k16.
// 4-stage cp.async pipeline, ONE __syncthreads per k32-chunk.
// ---------------------------------------------------------------------------
#define ROWB 80                            // padded row stride bytes (32 bf16 data)
#define TILE_B (128 * ROWB)                // 10240
#define STAGE_B (4 * TILE_B)               // Ah, Al, Bh, Bl = 40960
#define NSTAGE 4
#define MMA_SMEM (NSTAGE * STAGE_B)        // 163840

template <bool RELU, bool SPLITOUT>
__global__ __launch_bounds__(256, 1)
void mma_gemm_kernel(const __nv_bfloat16* __restrict__ Ah,
                     const __nv_bfloat16* __restrict__ Al,
                     const __nv_bfloat16* __restrict__ Bh,
                     const __nv_bfloat16* __restrict__ Bl,
                     float* __restrict__ C,
                     __nv_bfloat16* __restrict__ Ch,
                     __nv_bfloat16* __restrict__ Cl,
                     int N, int K,
                     const float* __restrict__ bias,
                     const float* __restrict__ residual)
{
    extern __shared__ char dsm[];
    const uint32_t sbase = smem_u32(dsm);

    const int tid = threadIdx.x;
    const int wid = tid >> 5;
    const int lane = tid & 31;
    const int bx = blockIdx.x, by = blockIdx.y;
    const int wm = wid & 1;          // 0..1 (M)
    const int wn = wid >> 1;         // 0..3 (N)

    const int lrow = tid >> 1;       // 0..127
    const int lh   = tid & 1;        // 32B half of the 64B row chunk
    const char* srcA_h = (const char*)(Ah + (size_t)(by*128 + lrow) * K);
    const char* srcA_l = (const char*)(Al + (size_t)(by*128 + lrow) * K);
    const char* srcB_h = (const char*)(Bh + (size_t)(bx*128 + lrow) * K);
    const char* srcB_l = (const char*)(Bl + (size_t)(bx*128 + lrow) * K);
    const uint32_t dst_row = lrow * ROWB + lh * 32;

    const int nck = K >> 5;          // 32 bf16 per chunk

    auto load_stage = [&](int stage, int i) {
        const size_t go = (size_t)i * 64 + lh * 32;
        const uint32_t d = sbase + stage * STAGE_B + dst_row;
        cp16(d + 0*TILE_B,      srcA_h + go);
        cp16(d + 0*TILE_B + 16, srcA_h + go + 16);
        cp16(d + 1*TILE_B,      srcA_l + go);
        cp16(d + 1*TILE_B + 16, srcA_l + go + 16);
        cp16(d + 2*TILE_B,      srcB_h + go);
        cp16(d + 2*TILE_B + 16, srcB_h + go + 16);
        cp16(d + 3*TILE_B,      srcB_l + go);
        cp16(d + 3*TILE_B + 16, srcB_l + go + 16);
        cp_commit();
    };

    float acc[4][4][4];
    #pragma unroll
    for (int mt = 0; mt < 4; mt++)
        #pragma unroll
        for (int nt = 0; nt < 4; nt++)
            #pragma unroll
            for (int e = 0; e < 4; e++) acc[mt][nt][e] = 0.f;

    load_stage(0, 0);
    load_stage(1, 1);
    load_stage(2, 2);

    const uint32_t aoff = (wm*64 + (lane & 15)) * ROWB + ((lane >> 4) & 1) * 16;
    const uint32_t boff = (wn*32 + (lane & 7) + ((lane >> 4) & 1) * 8) * ROWB
                        + ((lane >> 3) & 1) * 16;

    for (int i = 0; i < nck; i++) {
        cp_wait<2>();
        __syncthreads();               // single barrier per chunk

        const uint32_t base = sbase + (i % NSTAGE) * STAGE_B;
        #pragma unroll
        for (int kk = 0; kk < 2; kk++) {
            const uint32_t kb = kk * 32;
            uint32_t ah[4][4], al[4][4];
            #pragma unroll
            for (int mt = 0; mt < 4; mt++) {
                const uint32_t ao = aoff + mt * 16 * ROWB + kb;
                ldsm4(ah[mt], base + 0*TILE_B + ao);
                ldsm4(al[mt], base + 1*TILE_B + ao);
            }
            uint32_t bh[8], bl[8];
            #pragma unroll
            for (int nt2 = 0; nt2 < 2; nt2++) {
                const uint32_t bo = boff + nt2 * 16 * ROWB + kb;
                ldsm4(bh + nt2*4, base + 2*TILE_B + bo);
                ldsm4(bl + nt2*4, base + 3*TILE_B + bo);
            }
            #pragma unroll
            for (int mt = 0; mt < 4; mt++)
                #pragma unroll
                for (int nt = 0; nt < 4; nt++) {
                    mma16816(acc[mt][nt], ah[mt], bh + nt*2);
                    mma16816(acc[mt][nt], ah[mt], bl + nt*2);
                    mma16816(acc[mt][nt], al[mt], bh + nt*2);
                }
        }

        if (i + 3 < nck) load_stage((i + 3) % NSTAGE, i + 3);
    }

    // ---- epilogue ----
    const int r0 = by*128 + wm*64;
    const int c0 = bx*128 + wn*32;
    #pragma unroll
    for (int mt = 0; mt < 4; mt++) {
        #pragma unroll
        for (int nt = 0; nt < 4; nt++) {
            const int r = r0 + mt*16 + (lane >> 2);
            const int c = c0 + nt*8 + (lane & 3) * 2;
            #pragma unroll
            for (int half = 0; half < 2; half++) {
                const int rr = r + half * 8;
                float v0 = acc[mt][nt][half*2 + 0];
                float v1 = acc[mt][nt][half*2 + 1];
                if (bias) { v0 += bias[c]; v1 += bias[c + 1]; }
                if (RELU) { v0 = fmaxf(v0, 0.f); v1 = fmaxf(v1, 0.f); }
                if (SPLITOUT) {
                    unsigned h, l;
                    split_pair(v0, v1, h, l);
                    *(unsigned*)(Ch + (size_t)rr * N + c) = h;
                    *(unsigned*)(Cl + (size_t)rr * N + c) = l;
                } else {
                    if (residual) {
                        const float2 rv = *(const float2*)&residual[(size_t)rr * N + c];
                        v0 += rv.x; v1 += rv.y;
                    }
                    *(float2*)&C[(size_t)rr * N + c] = make_float2(v0, v1);
                }
            }
        }
    }
}

// ---------------------------------------------------------------------------
// Flash attention fp32, 4x4 micro-tile + f32x2; output written directly as
// bf16 hi/lo split (feeds the o-projection GEMM, no separate convert pass).
// ---------------------------------------------------------------------------
#define AL 68
#define ATT_SMEM_BYTES (4 * 64 * AL * (int)sizeof(float))   // 69632

template <bool CAUSAL>
__global__ __launch_bounds__(256)
void attn_kernel(const float* __restrict__ Q, const float* __restrict__ K,
                 const float* __restrict__ V,
                 __nv_bfloat16* __restrict__ Oh, __nv_bfloat16* __restrict__ Ol)
{
    extern __shared__ float sm[];
    float* Qs = sm;
    float* Ks = Qs + 64*AL;
    float* Vs = Ks + 64*AL;
    float* Pt = Vs + 64*AL;   // [key][query]

    const int qt = blockIdx.x, h = blockIdx.y, b = blockIdx.z;
    const int tid = threadIdx.x;
    const int tr = tid >> 4, tc = tid & 15;
    const int qr = tr * 4;
    const int dc = tc * 4;

    const size_t qbase = ((size_t)b*TT + qt*64) * CC + h*DD;

    {
        const int r = tid >> 2, c0 = (tid & 3) * 16;
        const float4* src = (const float4*)(Q + qbase + (size_t)r*CC + c0);
        float4* dst = (float4*)(Qs + r*AL + c0);
        dst[0] = src[0]; dst[1] = src[1]; dst[2] = src[2]; dst[3] = src[3];
    }

    ull o2[2][4];
    {
        const ull z = pack2(0.f, 0.f);
        #pragma unroll
        for (int i = 0; i < 2; i++)
            #pragma unroll
            for (int j = 0; j < 4; j++) o2[i][j] = z;
    }
    float m[4], l[4];
    #pragma unroll
    for (int i = 0; i < 4; i++) { m[i] = -CUDART_INF_F; l[i] = 0.f; }

    const int nkt = CAUSAL ? (qt + 1) : (TT / 64);

    for (int kt = 0; kt < nkt; kt++) {
        __syncthreads();
        {
            const size_t kbase = ((size_t)b*TT + kt*64) * CC + h*DD;
            const int r = tid >> 2, c0 = (tid & 3) * 16;
            const float4* ks = (const float4*)(K + kbase + (size_t)r*CC + c0);
            const float4* vs = (const float4*)(V + kbase + (size_t)r*CC + c0);
            float4* kd = (float4*)(Ks + r*AL + c0);
            float4* vd = (float4*)(Vs + r*AL + c0);
            #pragma unroll
            for (int i = 0; i < 4; i++) { kd[i] = ks[i]; vd[i] = vs[i]; }
        }
        __syncthreads();

        ull s2[4][4];
        {
            const ull z = pack2(0.f, 0.f);
            #pragma unroll
            for (int i = 0; i < 4; i++)
                #pragma unroll
                for (int j = 0; j < 4; j++) s2[i][j] = z;
        }
        #pragma unroll
        for (int d = 0; d < DD; d += 4) {
            const ulonglong2 q0 = *(const ulonglong2*)&Qs[(qr+0)*AL + d];
            const ulonglong2 q1 = *(const ulonglong2*)&Qs[(qr+1)*AL + d];
            const ulonglong2 q2 = *(const ulonglong2*)&Qs[(qr+2)*AL + d];
            const ulonglong2 q3 = *(const ulonglong2*)&Qs[(qr+3)*AL + d];
            const ulonglong2 k0 = *(const ulonglong2*)&Ks[(tc +  0)*AL + d];
            const ulonglong2 k1 = *(const ulonglong2*)&Ks[(tc + 16)*AL + d];
            const ulonglong2 k2 = *(const ulonglong2*)&Ks[(tc + 32)*AL + d];
            const ulonglong2 k3 = *(const ulonglong2*)&Ks[(tc + 48)*AL + d];
            fma2(s2[0][0], q0.x, k0.x); fma2(s2[0][0], q0.y, k0.y);
            fma2(s2[0][1], q0.x, k1.x); fma2(s2[0][1], q0.y, k1.y);
            fma2(s2[0][2], q0.x, k2.x); fma2(s2[0][2], q0.y, k2.y);
            fma2(s2[0][3], q0.x, k3.x); fma2(s2[0][3], q0.y, k3.y);
            fma2(s2[1][0], q1.x, k0.x); fma2(s2[1][0], q1.y, k0.y);
            fma2(s2[1][1], q1.x, k1.x); fma2(s2[1][1], q1.y, k1.y);
            fma2(s2[1][2], q1.x, k2.x); fma2(s2[1][2], q1.y, k2.y);
            fma2(s2[1][3], q1.x, k3.x); fma2(s2[1][3], q1.y, k3.y);
            fma2(s2[2][0], q2.x, k0.x); fma2(s2[2][0], q2.y, k0.y);
            fma2(s2[2][1], q2.x, k1.x); fma2(s2[2][1], q2.y, k1.y);
            fma2(s2[2][2], q2.x, k2.x); fma2(s2[2][2], q2.y, k2.y);
            fma2(s2[2][3], q2.x, k3.x); fma2(s2[2][3], q2.y, k3.y);
            fma2(s2[3][0], q3.x, k0.x); fma2(s2[3][0], q3.y, k0.y);
            fma2(s2[3][1], q3.x, k1.x); fma2(s2[3][1], q3.y, k1.y);
            fma2(s2[3][2], q3.x, k2.x); fma2(s2[3][2], q3.y, k2.y);
            fma2(s2[3][3], q3.x, k3.x); fma2(s2[3][3], q3.y, k3.y);
        }

        float s[4][4];
        #pragma unroll
        for (int i = 0; i < 4; i++)
            #pragma unroll
            for (int j = 0; j < 4; j++) {
                const float2 t = unpack2(s2[i][j]);
                s[i][j] = (t.x + t.y) * 0.125f;
            }

        if (CAUSAL && kt == qt) {
            #pragma unroll
            for (int i = 0; i < 4; i++)
                #pragma unroll
                for (int j = 0; j < 4; j++)
                    if (tc + 16*j > qr + i) s[i][j] = -CUDART_INF_F;
        }

        float corr[4];
        #pragma unroll
        for (int i = 0; i < 4; i++) {
            float mloc = fmaxf(fmaxf(s[i][0], s[i][1]), fmaxf(s[i][2], s[i][3]));
            #pragma unroll
            for (int o = 8; o; o >>= 1)
                mloc = fmaxf(mloc, __shfl_xor_sync(0xffffffffu, mloc, o));
            const float mn = fmaxf(m[i], mloc);
            corr[i] = __expf(m[i] - mn);
            m[i] = mn;
            float lsum = 0.f;
            #pragma unroll
            for (int j = 0; j < 4; j++) {
                const float p = __expf(s[i][j] - mn);
                s[i][j] = p;
                lsum += p;
            }
            #pragma unroll
            for (int o = 8; o; o >>= 1)
                lsum += __shfl_xor_sync(0xffffffffu, lsum, o);
            l[i] = l[i] * corr[i] + lsum;
        }

        {
            const ull c01 = pack2(corr[0], corr[1]);
            const ull c23 = pack2(corr[2], corr[3]);
            #pragma unroll
            for (int dj = 0; dj < 4; dj++) { mul2(o2[0][dj], c01); mul2(o2[1][dj], c23); }
        }

        #pragma unroll
        for (int j = 0; j < 4; j++)
            *(float4*)&Pt[(tc + 16*j)*AL + qr] =
                make_float4(s[0][j], s[1][j], s[2][j], s[3][j]);
        __syncwarp();
        __syncthreads();

        #pragma unroll 4
        for (int kj = 0; kj < 64; kj++) {
            const ulonglong2 p2 = *(const ulonglong2*)&Pt[kj*AL + qr];
            const float4 v = *(const float4*)&Vs[kj*AL + dc];
            const ull vx = pack2(v.x, v.x);
            const ull vy = pack2(v.y, v.y);
            const ull vz = pack2(v.z, v.z);
            const ull vw = pack2(v.w, v.w);
            fma2(o2[0][0], p2.x, vx); fma2(o2[0][1], p2.x, vy);
            fma2(o2[0][2], p2.x, vz); fma2(o2[0][3], p2.x, vw);
            fma2(o2[1][0], p2.y, vx); fma2(o2[1][1], p2.y, vy);
            fma2(o2[1][2], p2.y, vz); fma2(o2[1][3], p2.y, vw);
        }
    }

    float inv[4];
    #pragma unroll
    for (int i = 0; i < 4; i++) inv[i] = 1.f / l[i];

    float oo[4][4];
    #pragma unroll
    for (int dj = 0; dj < 4; dj++) {
        const float2 t0 = unpack2(o2[0][dj]);
        const float2 t1 = unpack2(o2[1][dj]);
        oo[0][dj] = t0.x * inv[0];
        oo[1][dj] = t0.y * inv[1];
        oo[2][dj] = t1.x * inv[2];
        oo[3][dj] = t1.y * inv[3];
    }
    #pragma unroll
    for (int i = 0; i < 4; i++) {
        uint2 hh, ll;
        split_pair(oo[i][0], oo[i][1], hh.x, ll.x);
        split_pair(oo[i][2], oo[i][3], hh.y, ll.y);
        const size_t off = qbase + (size_t)(qr + i) * CC + dc;
        *(uint2*)(Oh + off) = hh;
        *(uint2*)(Ol + off) = ll;
    }
}

// ---------------------------------------------------------------------------
// Host launcher
// ---------------------------------------------------------------------------
extern "C" void kernel_launch(void* const* d_in, const int* in_sizes, int n_in,
                              void* d_out, int out_size)
{
    (void)in_sizes; (void)n_in; (void)out_size;
    const float* x      = (const float*)d_in[0];
    const float* enc    = (const float*)d_in[1];
    const float* sa_wq  = (const float*)d_in[2];
    const float* sa_wk  = (const float*)d_in[3];
    const float* sa_wv  = (const float*)d_in[4];
    const float* sa_wo  = (const float*)d_in[5];
    const float* sa_bo  = (const float*)d_in[6];
    const float* ca_wq  = (const float*)d_in[7];
    const float* ca_wk  = (const float*)d_in[8];
    const float* ca_wv  = (const float*)d_in[9];
    const float* ca_wo  = (const float*)d_in[10];
    const float* ca_bo  = (const float*)d_in[11];
    const float* ff_w1  = (const float*)d_in[12];
    const float* ff_b1  = (const float*)d_in[13];
    const float* ff_w2  = (const float*)d_in[14];
    const float* ff_b2  = (const float*)d_in[15];
    const float* ln1_g  = (const float*)d_in[16];
    const float* ln1_b  = (const float*)d_in[17];
    const float* ln2_g  = (const float*)d_in[18];
    const float* ln2_b  = (const float*)d_in[19];
    const float* ln3_g  = (const float*)d_in[20];
    const float* ln3_b  = (const float*)d_in[21];
    float* out = (float*)d_out;

    float *q, *k, *v, *x1, *x2;
    __nv_bfloat16 *ah, *al, *ffh, *ffl, *wth, *wtl;
    cudaGetSymbolAddress((void**)&q,   g_q);
    cudaGetSymbolAddress((void**)&k,   g_k);
    cudaGetSymbolAddress((void**)&v,   g_v);
    cudaGetSymbolAddress((void**)&x1,  g_x1);
    cudaGetSymbolAddress((void**)&x2,  g_x2);
    cudaGetSymbolAddress((void**)&ah,  g_ah);
    cudaGetSymbolAddress((void**)&al,  g_al);
    cudaGetSymbolAddress((void**)&ffh, g_ffh);
    cudaGetSymbolAddress((void**)&ffl, g_ffl);
    cudaGetSymbolAddress((void**)&wth, g_wth);
    cudaGetSymbolAddress((void**)&wtl, g_wtl);

    cudaFuncSetAttribute(attn_kernel<true>,
                         cudaFuncAttributeMaxDynamicSharedMemorySize, ATT_SMEM_BYTES);
    cudaFuncSetAttribute(attn_kernel<false>,
                         cudaFuncAttributeMaxDynamicSharedMemorySize, ATT_SMEM_BYTES);
    cudaFuncSetAttribute(mma_gemm_kernel<false, false>,
                         cudaFuncAttributeMaxDynamicSharedMemorySize, MMA_SMEM);
    cudaFuncSetAttribute(mma_gemm_kernel<true, true>,
                         cudaFuncAttributeMaxDynamicSharedMemorySize, MMA_SMEM);

    const dim3 gCC(CC/128, MM/128);      // (8, 32)
    const dim3 gFF(FF/128, MM/128);      // (32, 32)
    const dim3 gAttn(TT/64, HH, BB);
    const dim3 gT1(CC/32, CC/32);
    const dim3 gT2(FF/32, CC/32);
    const dim3 gT3(CC/32, FF/32);
    const int cvt_blocks = (MM*CC/4 + 255) / 256;

    #define GEMM(AH, AL_, N_, K_, BIAS, RES, OUT) \
        mma_gemm_kernel<false,false><<<dim3((N_)/128, MM/128), 256, MMA_SMEM>>>( \
            AH, AL_, wth, wtl, OUT, nullptr, nullptr, N_, K_, BIAS, RES)

    // ---- self-attention ----
    ln_split_kernel<<<MM, 256>>>(x, ln1_g, ln1_b, ah, al);
    wtrans_split_kernel<<<gT1, 256>>>(sa_wq, wth, wtl, CC, CC);
    GEMM(ah, al, CC, CC, nullptr, nullptr, q);
    wtrans_split_kernel<<<gT1, 256>>>(sa_wk, wth, wtl, CC, CC);
    GEMM(ah, al, CC, CC, nullptr, nullptr, k);
    wtrans_split_kernel<<<gT1, 256>>>(sa_wv, wth, wtl, CC, CC);
    GEMM(ah, al, CC, CC, nullptr, nullptr, v);
    attn_kernel<true><<<gAttn, 256, ATT_SMEM_BYTES>>>(q, k, v, ah, al);
    wtrans_split_kernel<<<gT1, 256>>>(sa_wo, wth, wtl, CC, CC);
    GEMM(ah, al, CC, CC, sa_bo, x, x1);

    // ---- cross-attention ----
    ln_split_kernel<<<MM, 256>>>(x1, ln2_g, ln2_b, ah, al);
    wtrans_split_kernel<<<gT1, 256>>>(ca_wq, wth, wtl, CC, CC);
    GEMM(ah, al, CC, CC, nullptr, nullptr, q);
    convert_split_kernel<<<cvt_blocks, 256>>>(enc, ah, al, MM*CC/4);
    wtrans_split_kernel<<<gT1, 256>>>(ca_wk, wth, wtl, CC, CC);
    GEMM(ah, al, CC, CC, nullptr, nullptr, k);
    wtrans_split_kernel<<<gT1, 256>>>(ca_wv, wth, wtl, CC, CC);
    GEMM(ah, al, CC, CC, nullptr, nullptr, v);
    attn_kernel<false><<<gAttn, 256, ATT_SMEM_BYTES>>>(q, k, v, ah, al);
    wtrans_split_kernel<<<gT1, 256>>>(ca_wo, wth, wtl, CC, CC);
    GEMM(ah, al, CC, CC, ca_bo, x1, x2);

    // ---- FFN ----
    ln_split_kernel<<<MM, 256>>>(x2, ln3_g, ln3_b, ah, al);
    wtrans_split_kernel<<<gT2, 256>>>(ff_w1, wth, wtl, CC, FF);
    mma_gemm_kernel<true, true><<<gFF, 256, MMA_SMEM>>>(
        ah, al, wth, wtl, nullptr, ffh, ffl, FF, CC, ff_b1, nullptr);
    wtrans_split_kernel<<<gT3, 256>>>(ff_w2, wth, wtl, FF, CC);
    mma_gemm_kernel<false, false><<<gCC, 256, MMA_SMEM>>>(
        ffh, ffl, wth, wtl, out, nullptr, nullptr, CC, FF, ff_b2, x2);

    #undef GEMM
}

// round 10
// speedup vs baseline: 3.7997x; 1.0161x over previous
#include <cuda_runtime.h>
#include <cuda_bf16.h>
#include <math_constants.h>
#include <cstdint>

// Problem constants
#define BB 4
#define TT 1024
#define CC 1024
#define HH 16
#define DD 64
#define MM (BB*TT)          // 4096 rows
#define FF (4*CC)           // 4096 ffn dim

typedef unsigned long long ull;

// ---------------------------------------------------------------------------
// f32x2 packed helpers (attention kernel)
// ---------------------------------------------------------------------------
__device__ __forceinline__ void fma2(ull& d, ull a, ull b) {
    asm("fma.rn.f32x2 %0, %1, %2, %0;" : "+l"(d) : "l"(a), "l"(b));
}
__device__ __forceinline__ void mul2(ull& d, ull a) {
    asm("mul.rn.f32x2 %0, %0, %1;" : "+l"(d) : "l"(a));
}
__device__ __forceinline__ ull pack2(float x, float y) {
    ull r;
    asm("mov.b64 %0, {%1, %2};" : "=l"(r)
        : "r"(__float_as_uint(x)), "r"(__float_as_uint(y)));
    return r;
}
__device__ __forceinline__ float2 unpack2(ull v) {
    unsigned lo, hi;
    asm("mov.b64 {%0, %1}, %2;" : "=r"(lo), "=r"(hi) : "l"(v));
    return make_float2(__uint_as_float(lo), __uint_as_float(hi));
}

// ---------------------------------------------------------------------------
// mma.sync / ldmatrix / cp.async helpers
// ---------------------------------------------------------------------------
__device__ __forceinline__ uint32_t smem_u32(const void* p) {
    uint32_t a;
    asm("{ .reg .u64 t; cvta.to.shared.u64 t, %1; cvt.u32.u64 %0, t; }"
        : "=r"(a) : "l"(p));
    return a;
}
__device__ __forceinline__ void ldsm4(uint32_t* r, uint32_t addr) {
    asm volatile("ldmatrix.sync.aligned.m8n8.x4.shared.b16 {%0,%1,%2,%3}, [%4];"
        : "=r"(r[0]), "=r"(r[1]), "=r"(r[2]), "=r"(r[3]) : "r"(addr));
}
__device__ __forceinline__ void mma16816(float* c, const uint32_t* a, const uint32_t* b) {
    asm volatile(
        "mma.sync.aligned.m16n8k16.row.col.f32.bf16.bf16.f32 "
        "{%0,%1,%2,%3}, {%4,%5,%6,%7}, {%8,%9}, {%0,%1,%2,%3};"
        : "+f"(c[0]), "+f"(c[1]), "+f"(c[2]), "+f"(c[3])
        : "r"(a[0]), "r"(a[1]), "r"(a[2]), "r"(a[3]), "r"(b[0]), "r"(b[1]));
}
__device__ __forceinline__ void cp16(uint32_t dst, const void* src) {
    asm volatile("cp.async.cg.shared.global [%0], [%1], 16;" :: "r"(dst), "l"(src));
}
__device__ __forceinline__ void cp_commit() {
    asm volatile("cp.async.commit_group;");
}
template <int N>
__device__ __forceinline__ void cp_wait() {
    asm volatile("cp.async.wait_group %0;" :: "n"(N));
}

// ---------------------------------------------------------------------------
// bf16 split helpers
// ---------------------------------------------------------------------------
__device__ __forceinline__ void split_pair(float a, float b, unsigned& h, unsigned& l) {
    __nv_bfloat16 ha = __float2bfloat16_rn(a);
    __nv_bfloat16 hb = __float2bfloat16_rn(b);
    __nv_bfloat16 la = __float2bfloat16_rn(a - __bfloat162float(ha));
    __nv_bfloat16 lb = __float2bfloat16_rn(b - __bfloat162float(hb));
    __nv_bfloat162 hp; hp.x = ha; hp.y = hb;
    __nv_bfloat162 lp; lp.x = la; lp.y = lb;
    h = *reinterpret_cast<unsigned*>(&hp);
    l = *reinterpret_cast<unsigned*>(&lp);
}

// ---------------------------------------------------------------------------
// Scratch (device globals)
// ---------------------------------------------------------------------------
__device__ float g_qkv[MM*3*CC];   // fused self-attn q|k|v, row stride 3072
__device__ float g_kv [MM*2*CC];   // fused cross-attn k|v, row stride 2048
__device__ float g_q  [MM*CC];     // cross-attn q
__device__ float g_x1 [MM*CC];
__device__ float g_x2 [MM*CC];
__device__ __nv_bfloat16 g_ah [MM*CC];
__device__ __nv_bfloat16 g_al [MM*CC];
__device__ __nv_bfloat16 g_ffh[MM*FF];
__device__ __nv_bfloat16 g_ffl[MM*FF];
__device__ __nv_bfloat16 g_wth[CC*FF];
__device__ __nv_bfloat16 g_wtl[CC*FF];

// ---------------------------------------------------------------------------
// LayerNorm emitting bf16 hi/lo split
// ---------------------------------------------------------------------------
__global__ __launch_bounds__(256)
void ln_split_kernel(const float* __restrict__ x, const float* __restrict__ gamma,
                     const float* __restrict__ beta,
                     __nv_bfloat16* __restrict__ oh, __nv_bfloat16* __restrict__ ol)
{
    __shared__ float red[8];
    const int row = blockIdx.x;
    const int t = threadIdx.x;
    const float4 v = ((const float4*)(x + (size_t)row * CC))[t];

    float s = v.x + v.y + v.z + v.w;
    #pragma unroll
    for (int o = 16; o; o >>= 1) s += __shfl_xor_sync(0xffffffffu, s, o);
    if ((t & 31) == 0) red[t >> 5] = s;
    __syncthreads();
    float tot = 0.f;
    #pragma unroll
    for (int i = 0; i < 8; i++) tot += red[i];
    const float mu = tot * (1.0f / CC);
    __syncthreads();

    const float dx = v.x - mu, dy = v.y - mu, dz = v.z - mu, dw = v.w - mu;
    float s2 = dx*dx + dy*dy + dz*dz + dw*dw;
    #pragma unroll
    for (int o = 16; o; o >>= 1) s2 += __shfl_xor_sync(0xffffffffu, s2, o);
    if ((t & 31) == 0) red[t >> 5] = s2;
    __syncthreads();
    float tot2 = 0.f;
    #pragma unroll
    for (int i = 0; i < 8; i++) tot2 += red[i];
    const float inv = rsqrtf(tot2 * (1.0f / CC) + 1e-5f);

    const float4 g4 = ((const float4*)gamma)[t];
    const float4 b4 = ((const float4*)beta)[t];
    const float y0 = dx * inv * g4.x + b4.x;
    const float y1 = dy * inv * g4.y + b4.y;
    const float y2 = dz * inv * g4.z + b4.z;
    const float y3 = dw * inv * g4.w + b4.w;

    uint2 hh, ll;
    split_pair(y0, y1, hh.x, ll.x);
    split_pair(y2, y3, hh.y, ll.y);
    ((uint2*)(oh + (size_t)row * CC))[t] = hh;
    ((uint2*)(ol + (size_t)row * CC))[t] = ll;
}

// ---------------------------------------------------------------------------
// Elementwise fp32 -> bf16 hi/lo (for enc)
// ---------------------------------------------------------------------------
__global__ __launch_bounds__(256)
void convert_split_kernel(const float* __restrict__ in,
                          __nv_bfloat16* __restrict__ oh,
                          __nv_bfloat16* __restrict__ ol, int n4)
{
    const int i = blockIdx.x * 256 + threadIdx.x;
    if (i >= n4) return;
    const float4 v = ((const float4*)in)[i];
    uint2 hh, ll;
    split_pair(v.x, v.y, hh.x, ll.x);
    split_pair(v.z, v.w, hh.y, ll.y);
    ((uint2*)oh)[i] = hh;
    ((uint2*)ol)[i] = ll;
}

// ---------------------------------------------------------------------------
// Weight transpose + split: W[K,N] fp32 -> Wt_hi/lo[N,K] bf16
// ---------------------------------------------------------------------------
__global__ __launch_bounds__(256)
void wtrans_split_kernel(const float* __restrict__ W,
                         __nv_bfloat16* __restrict__ th,
                         __nv_bfloat16* __restrict__ tl, int K, int N)
{
    __shared__ float tile[32][33];
    const int bx = blockIdx.x;
    const int by = blockIdx.y;
    const int tx = threadIdx.x & 31;
    const int ty = threadIdx.x >> 5;
    #pragma unroll
    for (int i = 0; i < 32; i += 8)
        tile[ty + i][tx] = W[(size_t)(by*32 + ty + i) * N + bx*32 + tx];
    __syncthreads();
    #pragma unroll
    for (int i = 0; i < 32; i += 8) {
        const float v = tile[tx][ty + i];
        const __nv_bfloat16 h = __float2bfloat16_rn(v);
        const __nv_bfloat16 l = __float2bfloat16_rn(v - __bfloat162float(h));
        const size_t o = (size_t)(bx*32 + ty + i) * K + by*32 + tx;
        th[o] = h;
        tl[o] = l;
    }
}

// ---------------------------------------------------------------------------
// HMMA GEMM: D[M,N] = A[M,K] @ Wt[N,K]^T, 3-way bf16 split, fp32 accum.
// 128x128 CTA tile, 16 warps (4 M x 4 N), warp tile 32x32, m16n8k16.
// 4-stage cp.async pipeline, one __syncthreads per k32-chunk.
// ---------------------------------------------------------------------------
#define ROWB 80                            // padded row stride bytes (32 bf16 data)
#define TILE_B (128 * ROWB)                // 10240
#define STAGE_B (4 * TILE_B)               // Ah, Al, Bh, Bl = 40960
#define NSTAGE 4
#define MMA_SMEM (NSTAGE * STAGE_B)        // 163840

template <bool RELU, bool SPLITOUT>
__global__ __launch_bounds__(512, 1)
void mma_gemm_kernel(const __nv_bfloat16* __restrict__ Ah,
                     const __nv_bfloat16* __restrict__ Al,
                     const __nv_bfloat16* __restrict__ Bh,
                     const __nv_bfloat16* __restrict__ Bl,
                     float* __restrict__ C,
                     __nv_bfloat16* __restrict__ Ch,
                     __nv_bfloat16* __restrict__ Cl,
                     int N, int K,
                     const float* __restrict__ bias,
                     const float* __restrict__ residual)
{
    extern __shared__ char dsm[];
    const uint32_t sbase = smem_u32(dsm);

    const int tid = threadIdx.x;
    const int wid = tid >> 5;
    const int lane = tid & 31;
    const int bx = blockIdx.x, by = blockIdx.y;
    const int wm = wid & 3;          // 0..3 (M)
    const int wn = wid >> 2;         // 0..3 (N)

    const int lrow = tid >> 2;       // 0..127
    const int lq   = tid & 3;        // 16B quarter of the 64B row chunk
    const char* srcA_h = (const char*)(Ah + (size_t)(by*128 + lrow) * K);
    const char* srcA_l = (const char*)(Al + (size_t)(by*128 + lrow) * K);
    const char* srcB_h = (const char*)(Bh + (size_t)(bx*128 + lrow) * K);
    const char* srcB_l = (const char*)(Bl + (size_t)(bx*128 + lrow) * K);
    const uint32_t dst_row = lrow * ROWB + lq * 16;

    const int nck = K >> 5;          // 32 bf16 per chunk

    auto load_stage = [&](int stage, int i) {
        const size_t go = (size_t)i * 64 + lq * 16;
        const uint32_t d = sbase + stage * STAGE_B + dst_row;
        cp16(d + 0*TILE_B, srcA_h + go);
        cp16(d + 1*TILE_B, srcA_l + go);
        cp16(d + 2*TILE_B, srcB_h + go);
        cp16(d + 3*TILE_B, srcB_l + go);
        cp_commit();
    };

    float acc[2][4][4];
    #pragma unroll
    for (int mt = 0; mt < 2; mt++)
        #pragma unroll
        for (int nt = 0; nt < 4; nt++)
            #pragma unroll
            for (int e = 0; e < 4; e++) acc[mt][nt][e] = 0.f;

    load_stage(0, 0);
    load_stage(1, 1);
    load_stage(2, 2);

    const uint32_t aoff = (wm*32 + (lane & 15)) * ROWB + ((lane >> 4) & 1) * 16;
    const uint32_t boff = (wn*32 + (lane & 7) + ((lane >> 4) & 1) * 8) * ROWB
                        + ((lane >> 3) & 1) * 16;

    for (int i = 0; i < nck; i++) {
        cp_wait<2>();
        __syncthreads();

        const uint32_t base = sbase + (i % NSTAGE) * STAGE_B;
        #pragma unroll
        for (int kk = 0; kk < 2; kk++) {
            const uint32_t kb = kk * 32;
            uint32_t ah[2][4], al[2][4];
            #pragma unroll
            for (int mt = 0; mt < 2; mt++) {
                const uint32_t ao = aoff + mt * 16 * ROWB + kb;
                ldsm4(ah[mt], base + 0*TILE_B + ao);
                ldsm4(al[mt], base + 1*TILE_B + ao);
            }
            uint32_t bh[8], bl[8];
            #pragma unroll
            for (int nt2 = 0; nt2 < 2; nt2++) {
                const uint32_t bo = boff + nt2 * 16 * ROWB + kb;
                ldsm4(bh + nt2*4, base + 2*TILE_B + bo);
                ldsm4(bl + nt2*4, base + 3*TILE_B + bo);
            }
            #pragma unroll
            for (int mt = 0; mt < 2; mt++)
                #pragma unroll
                for (int nt = 0; nt < 4; nt++) {
                    mma16816(acc[mt][nt], ah[mt], bh + nt*2);
                    mma16816(acc[mt][nt], ah[mt], bl + nt*2);
                    mma16816(acc[mt][nt], al[mt], bh + nt*2);
                }
        }

        if (i + 3 < nck) load_stage((i + 3) % NSTAGE, i + 3);
    }

    // ---- epilogue ----
    const int r0 = by*128 + wm*32;
    const int c0 = bx*128 + wn*32;
    #pragma unroll
    for (int mt = 0; mt < 2; mt++) {
        #pragma unroll
        for (int nt = 0; nt < 4; nt++) {
            const int r = r0 + mt*16 + (lane >> 2);
            const int c = c0 + nt*8 + (lane & 3) * 2;
            #pragma unroll
            for (int half = 0; half < 2; half++) {
                const int rr = r + half * 8;
                float v0 = acc[mt][nt][half*2 + 0];
                float v1 = acc[mt][nt][half*2 + 1];
                if (bias) { v0 += bias[c]; v1 += bias[c + 1]; }
                if (RELU) { v0 = fmaxf(v0, 0.f); v1 = fmaxf(v1, 0.f); }
                if (SPLITOUT) {
                    unsigned h, l;
                    split_pair(v0, v1, h, l);
                    *(unsigned*)(Ch + (size_t)rr * N + c) = h;
                    *(unsigned*)(Cl + (size_t)rr * N + c) = l;
                } else {
                    if (residual) {
                        const float2 rv = *(const float2*)&residual[(size_t)rr * N + c];
                        v0 += rv.x; v1 += rv.y;
                    }
                    *(float2*)&C[(size_t)rr * N + c] = make_float2(v0, v1);
                }
            }
        }
    }
}

// ---------------------------------------------------------------------------
// Flash attention fp32, 4x4 micro-tile + f32x2. Runtime row strides so Q/K/V
// can live in fused projection outputs. Output: bf16 hi/lo split (stride CC).
// ---------------------------------------------------------------------------
#define AL 68
#define ATT_SMEM_BYTES (4 * 64 * AL * (int)sizeof(float))   // 69632

template <bool CAUSAL>
__global__ __launch_bounds__(256)
void attn_kernel(const float* __restrict__ Q, const float* __restrict__ K,
                 const float* __restrict__ V, int sQ, int sKV,
                 __nv_bfloat16* __restrict__ Oh, __nv_bfloat16* __restrict__ Ol)
{
    extern __shared__ float sm[];
    float* Qs = sm;
    float* Ks = Qs + 64*AL;
    float* Vs = Ks + 64*AL;
    float* Pt = Vs + 64*AL;   // [key][query]

    const int qt = blockIdx.x, h = blockIdx.y, b = blockIdx.z;
    const int tid = threadIdx.x;
    const int tr = tid >> 4, tc = tid & 15;
    const int qr = tr * 4;
    const int dc = tc * 4;

    const size_t qrow0 = (size_t)b*TT + qt*64;

    {
        const int r = tid >> 2, c0 = (tid & 3) * 16;
        const float4* src = (const float4*)(Q + (qrow0 + r) * sQ + h*DD + c0);
        float4* dst = (float4*)(Qs + r*AL + c0);
        dst[0] = src[0]; dst[1] = src[1]; dst[2] = src[2]; dst[3] = src[3];
    }

    ull o2[2][4];
    {
        const ull z = pack2(0.f, 0.f);
        #pragma unroll
        for (int i = 0; i < 2; i++)
            #pragma unroll
            for (int j = 0; j < 4; j++) o2[i][j] = z;
    }
    float m[4], l[4];
    #pragma unroll
    for (int i = 0; i < 4; i++) { m[i] = -CUDART_INF_F; l[i] = 0.f; }

    const int nkt = CAUSAL ? (qt + 1) : (TT / 64);

    for (int kt = 0; kt < nkt; kt++) {
        __syncthreads();
        {
            const size_t krow0 = (size_t)b*TT + kt*64;
            const int r = tid >> 2, c0 = (tid & 3) * 16;
            const float4* ks = (const float4*)(K + (krow0 + r) * sKV + h*DD + c0);
            const float4* vs = (const float4*)(V + (krow0 + r) * sKV + h*DD + c0);
            float4* kd = (float4*)(Ks + r*AL + c0);
            float4* vd = (float4*)(Vs + r*AL + c0);
            #pragma unroll
            for (int i = 0; i < 4; i++) { kd[i] = ks[i]; vd[i] = vs[i]; }
        }
        __syncthreads();

        ull s2[4][4];
        {
            const ull z = pack2(0.f, 0.f);
            #pragma unroll
            for (int i = 0; i < 4; i++)
                #pragma unroll
                for (int j = 0; j < 4; j++) s2[i][j] = z;
        }
        #pragma unroll
        for (int d = 0; d < DD; d += 4) {
            const ulonglong2 q0 = *(const ulonglong2*)&Qs[(qr+0)*AL + d];
            const ulonglong2 q1 = *(const ulonglong2*)&Qs[(qr+1)*AL + d];
            const ulonglong2 q2 = *(const ulonglong2*)&Qs[(qr+2)*AL + d];
            const ulonglong2 q3 = *(const ulonglong2*)&Qs[(qr+3)*AL + d];
            const ulonglong2 k0 = *(const ulonglong2*)&Ks[(tc +  0)*AL + d];
            const ulonglong2 k1 = *(const ulonglong2*)&Ks[(tc + 16)*AL + d];
            const ulonglong2 k2 = *(const ulonglong2*)&Ks[(tc + 32)*AL + d];
            const ulonglong2 k3 = *(const ulonglong2*)&Ks[(tc + 48)*AL + d];
            fma2(s2[0][0], q0.x, k0.x); fma2(s2[0][0], q0.y, k0.y);
            fma2(s2[0][1], q0.x, k1.x); fma2(s2[0][1], q0.y, k1.y);
            fma2(s2[0][2], q0.x, k2.x); fma2(s2[0][2], q0.y, k2.y);
            fma2(s2[0][3], q0.x, k3.x); fma2(s2[0][3], q0.y, k3.y);
            fma2(s2[1][0], q1.x, k0.x); fma2(s2[1][0], q1.y, k0.y);
            fma2(s2[1][1], q1.x, k1.x); fma2(s2[1][1], q1.y, k1.y);
            fma2(s2[1][2], q1.x, k2.x); fma2(s2[1][2], q1.y, k2.y);
            fma2(s2[1][3], q1.x, k3.x); fma2(s2[1][3], q1.y, k3.y);
            fma2(s2[2][0], q2.x, k0.x); fma2(s2[2][0], q2.y, k0.y);
            fma2(s2[2][1], q2.x, k1.x); fma2(s2[2][1], q2.y, k1.y);
            fma2(s2[2][2], q2.x, k2.x); fma2(s2[2][2], q2.y, k2.y);
            fma2(s2[2][3], q2.x, k3.x); fma2(s2[2][3], q2.y, k3.y);
            fma2(s2[3][0], q3.x, k0.x); fma2(s2[3][0], q3.y, k0.y);
            fma2(s2[3][1], q3.x, k1.x); fma2(s2[3][1], q3.y, k1.y);
            fma2(s2[3][2], q3.x, k2.x); fma2(s2[3][2], q3.y, k2.y);
            fma2(s2[3][3], q3.x, k3.x); fma2(s2[3][3], q3.y, k3.y);
        }

        float s[4][4];
        #pragma unroll
        for (int i = 0; i < 4; i++)
            #pragma unroll
            for (int j = 0; j < 4; j++) {
                const float2 t = unpack2(s2[i][j]);
                s[i][j] = (t.x + t.y) * 0.125f;
            }

        if (CAUSAL && kt == qt) {
            #pragma unroll
            for (int i = 0; i < 4; i++)
                #pragma unroll
                for (int j = 0; j < 4; j++)
                    if (tc + 16*j > qr + i) s[i][j] = -CUDART_INF_F;
        }

        float corr[4];
        #pragma unroll
        for (int i = 0; i < 4; i++) {
            float mloc = fmaxf(fmaxf(s[i][0], s[i][1]), fmaxf(s[i][2], s[i][3]));
            #pragma unroll
            for (int o = 8; o; o >>= 1)
                mloc = fmaxf(mloc, __shfl_xor_sync(0xffffffffu, mloc, o));
            const float mn = fmaxf(m[i], mloc);
            corr[i] = __expf(m[i] - mn);
            m[i] = mn;
            float lsum = 0.f;
            #pragma unroll
            for (int j = 0; j < 4; j++) {
                const float p = __expf(s[i][j] - mn);
                s[i][j] = p;
                lsum += p;
            }
            #pragma unroll
            for (int o = 8; o; o >>= 1)
                lsum += __shfl_xor_sync(0xffffffffu, lsum, o);
            l[i] = l[i] * corr[i] + lsum;
        }

        {
            const ull c01 = pack2(corr[0], corr[1]);
            const ull c23 = pack2(corr[2], corr[3]);
            #pragma unroll
            for (int dj = 0; dj < 4; dj++) { mul2(o2[0][dj], c01); mul2(o2[1][dj], c23); }
        }

        #pragma unroll
        for (int j = 0; j < 4; j++)
            *(float4*)&Pt[(tc + 16*j)*AL + qr] =
                make_float4(s[0][j], s[1][j], s[2][j], s[3][j]);
        __syncwarp();
        __syncthreads();

        #pragma unroll 4
        for (int kj = 0; kj < 64; kj++) {
            const ulonglong2 p2 = *(const ulonglong2*)&Pt[kj*AL + qr];
            const float4 v = *(const float4*)&Vs[kj*AL + dc];
            const ull vx = pack2(v.x, v.x);
            const ull vy = pack2(v.y, v.y);
            const ull vz = pack2(v.z, v.z);
            const ull vw = pack2(v.w, v.w);
            fma2(o2[0][0], p2.x, vx); fma2(o2[0][1], p2.x, vy);
            fma2(o2[0][2], p2.x, vz); fma2(o2[0][3], p2.x, vw);
            fma2(o2[1][0], p2.y, vx); fma2(o2[1][1], p2.y, vy);
            fma2(o2[1][2], p2.y, vz); fma2(o2[1][3], p2.y, vw);
        }
    }

    float inv[4];
    #pragma unroll
    for (int i = 0; i < 4; i++) inv[i] = 1.f / l[i];

    float oo[4][4];
    #pragma unroll
    for (int dj = 0; dj < 4; dj++) {
        const float2 t0 = unpack2(o2[0][dj]);
        const float2 t1 = unpack2(o2[1][dj]);
        oo[0][dj] = t0.x * inv[0];
        oo[1][dj] = t0.y * inv[1];
        oo[2][dj] = t1.x * inv[2];
        oo[3][dj] = t1.y * inv[3];
    }
    #pragma unroll
    for (int i = 0; i < 4; i++) {
        uint2 hh, ll;
        split_pair(oo[i][0], oo[i][1], hh.x, ll.x);
        split_pair(oo[i][2], oo[i][3], hh.y, ll.y);
        const size_t off = (qrow0 + qr + i) * CC + h*DD + dc;
        *(uint2*)(Oh + off) = hh;
        *(uint2*)(Ol + off) = ll;
    }
}

// ---------------------------------------------------------------------------
// Host launcher
// ---------------------------------------------------------------------------
extern "C" void kernel_launch(void* const* d_in, const int* in_sizes, int n_in,
                              void* d_out, int out_size)
{
    (void)in_sizes; (void)n_in; (void)out_size;
    const float* x      = (const float*)d_in[0];
    const float* enc    = (const float*)d_in[1];
    const float* sa_wq  = (const float*)d_in[2];
    const float* sa_wk  = (const float*)d_in[3];
    const float* sa_wv  = (const float*)d_in[4];
    const float* sa_wo  = (const float*)d_in[5];
    const float* sa_bo  = (const float*)d_in[6];
    const float* ca_wq  = (const float*)d_in[7];
    const float* ca_wk  = (const float*)d_in[8];
    const float* ca_wv  = (const float*)d_in[9];
    const float* ca_wo  = (const float*)d_in[10];
    const float* ca_bo  = (const float*)d_in[11];
    const float* ff_w1  = (const float*)d_in[12];
    const float* ff_b1  = (const float*)d_in[13];
    const float* ff_w2  = (const float*)d_in[14];
    const float* ff_b2  = (const float*)d_in[15];
    const float* ln1_g  = (const float*)d_in[16];
    const float* ln1_b  = (const float*)d_in[17];
    const float* ln2_g  = (const float*)d_in[18];
    const float* ln2_b  = (const float*)d_in[19];
    const float* ln3_g  = (const float*)d_in[20];
    const float* ln3_b  = (const float*)d_in[21];
    float* out = (float*)d_out;

    float *qkv, *kv, *q, *x1, *x2;
    __nv_bfloat16 *ah, *al, *ffh, *ffl, *wth, *wtl;
    cudaGetSymbolAddress((void**)&qkv, g_qkv);
    cudaGetSymbolAddress((void**)&kv,  g_kv);
    cudaGetSymbolAddress((void**)&q,   g_q);
    cudaGetSymbolAddress((void**)&x1,  g_x1);
    cudaGetSymbolAddress((void**)&x2,  g_x2);
    cudaGetSymbolAddress((void**)&ah,  g_ah);
    cudaGetSymbolAddress((void**)&al,  g_al);
    cudaGetSymbolAddress((void**)&ffh, g_ffh);
    cudaGetSymbolAddress((void**)&ffl, g_ffl);
    cudaGetSymbolAddress((void**)&wth, g_wth);
    cudaGetSymbolAddress((void**)&wtl, g_wtl);

    cudaFuncSetAttribute(attn_kernel<true>,
                         cudaFuncAttributeMaxDynamicSharedMemorySize, ATT_SMEM_BYTES);
    cudaFuncSetAttribute(attn_kernel<false>,
                         cudaFuncAttributeMaxDynamicSharedMemorySize, ATT_SMEM_BYTES);
    cudaFuncSetAttribute(mma_gemm_kernel<false, false>,
                         cudaFuncAttributeMaxDynamicSharedMemorySize, MMA_SMEM);
    cudaFuncSetAttribute(mma_gemm_kernel<true, true>,
                         cudaFuncAttributeMaxDynamicSharedMemorySize, MMA_SMEM);

    const dim3 gAttn(TT/64, HH, BB);
    const dim3 gT1(CC/32, CC/32);
    const dim3 gT2(FF/32, CC/32);
    const dim3 gT3(CC/32, FF/32);
    const int cvt_blocks = (MM*CC/4 + 255) / 256;

    #define GEMM(N_, K_, BIAS, RES, OUT) \
        mma_gemm_kernel<false,false><<<dim3((N_)/128, MM/128), 512, MMA_SMEM>>>( \
            ah, al, wth, wtl, OUT, nullptr, nullptr, N_, K_, BIAS, RES)

    // ---- self-attention ----
    ln_split_kernel<<<MM, 256>>>(x, ln1_g, ln1_b, ah, al);
    wtrans_split_kernel<<<gT1, 256>>>(sa_wq, wth + 0*CC*CC, wtl + 0*CC*CC, CC, CC);
    wtrans_split_kernel<<<gT1, 256>>>(sa_wk, wth + 1*CC*CC, wtl + 1*CC*CC, CC, CC);
    wtrans_split_kernel<<<gT1, 256>>>(sa_wv, wth + 2*CC*CC, wtl + 2*CC*CC, CC, CC);
    GEMM(3*CC, CC, nullptr, nullptr, qkv);                    // fused q|k|v
    attn_kernel<true><<<gAttn, 256, ATT_SMEM_BYTES>>>(
        qkv, qkv + CC, qkv + 2*CC, 3*CC, 3*CC, ah, al);
    wtrans_split_kernel<<<gT1, 256>>>(sa_wo, wth, wtl, CC, CC);
    GEMM(CC, CC, sa_bo, x, x1);

    // ---- cross-attention ----
    ln_split_kernel<<<MM, 256>>>(x1, ln2_g, ln2_b, ah, al);
    wtrans_split_kernel<<<gT1, 256>>>(ca_wq, wth, wtl, CC, CC);
    GEMM(CC, CC, nullptr, nullptr, q);
    convert_split_kernel<<<cvt_blocks, 256>>>(enc, ah, al, MM*CC/4);
    wtrans_split_kernel<<<gT1, 256>>>(ca_wk, wth + 0*CC*CC, wtl + 0*CC*CC, CC, CC);
    wtrans_split_kernel<<<gT1, 256>>>(ca_wv, wth + 1*CC*CC, wtl + 1*CC*CC, CC, CC);
    GEMM(2*CC, CC, nullptr, nullptr, kv);                     // fused k|v
    attn_kernel<false><<<gAttn, 256, ATT_SMEM_BYTES>>>(
        q, kv, kv + CC, CC, 2*CC, ah, al);
    wtrans_split_kernel<<<gT1, 256>>>(ca_wo, wth, wtl, CC, CC);
    GEMM(CC, CC, ca_bo, x1, x2);

    // ---- FFN ----
    ln_split_kernel<<<MM, 256>>>(x2, ln3_g, ln3_b, ah, al);
    wtrans_split_kernel<<<gT2, 256>>>(ff_w1, wth, wtl, CC, FF);
    mma_gemm_kernel<true, true><<<dim3(FF/128, MM/128), 512, MMA_SMEM>>>(
        ah, al, wth, wtl, nullptr, ffh, ffl, FF, CC, ff_b1, nullptr);
    wtrans_split_kernel<<<gT3, 256>>>(ff_w2, wth, wtl, FF, CC);
    mma_gemm_kernel<false, false><<<dim3(CC/128, MM/128), 512, MMA_SMEM>>>(
        ffh, ffl, wth, wtl, out, nullptr, nullptr, CC, FF, ff_b2, x2);

    #undef GEMM
}

// round 11
// speedup vs baseline: 5.8262x; 1.5333x over previous
#include <cuda_runtime.h>
#include <cuda_bf16.h>
#include <cuda_fp16.h>
#include <math_constants.h>
#include <cstdint>

// Problem constants
#define BB 4
#define TT 1024
#define CC 1024
#define HH 16
#define DD 64
#define MM (BB*TT)          // 4096 rows
#define FF (4*CC)           // 4096 ffn dim

typedef unsigned long long ull;

// ---------------------------------------------------------------------------
// f32x2 packed helpers (attention kernel)
// ---------------------------------------------------------------------------
__device__ __forceinline__ void fma2(ull& d, ull a, ull b) {
    asm("fma.rn.f32x2 %0, %1, %2, %0;" : "+l"(d) : "l"(a), "l"(b));
}
__device__ __forceinline__ void mul2(ull& d, ull a) {
    asm("mul.rn.f32x2 %0, %0, %1;" : "+l"(d) : "l"(a));
}
__device__ __forceinline__ ull pack2(float x, float y) {
    ull r;
    asm("mov.b64 %0, {%1, %2};" : "=l"(r)
        : "r"(__float_as_uint(x)), "r"(__float_as_uint(y)));
    return r;
}
__device__ __forceinline__ float2 unpack2(ull v) {
    unsigned lo, hi;
    asm("mov.b64 {%0, %1}, %2;" : "=r"(lo), "=r"(hi) : "l"(v));
    return make_float2(__uint_as_float(lo), __uint_as_float(hi));
}

// ---------------------------------------------------------------------------
// mma.sync / ldmatrix / cp.async helpers
// ---------------------------------------------------------------------------
__device__ __forceinline__ uint32_t smem_u32(const void* p) {
    uint32_t a;
    asm("{ .reg .u64 t; cvta.to.shared.u64 t, %1; cvt.u32.u64 %0, t; }"
        : "=r"(a) : "l"(p));
    return a;
}
__device__ __forceinline__ void ldsm4(uint32_t* r, uint32_t addr) {
    asm volatile("ldmatrix.sync.aligned.m8n8.x4.shared.b16 {%0,%1,%2,%3}, [%4];"
        : "=r"(r[0]), "=r"(r[1]), "=r"(r[2]), "=r"(r[3]) : "r"(addr));
}
__device__ __forceinline__ void mma16816(float* c, const uint32_t* a, const uint32_t* b) {
    asm volatile(
        "mma.sync.aligned.m16n8k16.row.col.f32.f16.f16.f32 "
        "{%0,%1,%2,%3}, {%4,%5,%6,%7}, {%8,%9}, {%0,%1,%2,%3};"
        : "+f"(c[0]), "+f"(c[1]), "+f"(c[2]), "+f"(c[3])
        : "r"(a[0]), "r"(a[1]), "r"(a[2]), "r"(a[3]), "r"(b[0]), "r"(b[1]));
}
__device__ __forceinline__ void cp16(uint32_t dst, const void* src) {
    asm volatile("cp.async.cg.shared.global [%0], [%1], 16;" :: "r"(dst), "l"(src));
}
__device__ __forceinline__ void cp_commit() {
    asm volatile("cp.async.commit_group;");
}
template <int N>
__device__ __forceinline__ void cp_wait() {
    asm volatile("cp.async.wait_group %0;" :: "n"(N));
}

// fp32 pair -> packed half2
__device__ __forceinline__ unsigned pack_h2(float a, float b) {
    __half2 h = __floats2half2_rn(a, b);
    return *reinterpret_cast<unsigned*>(&h);
}

// ---------------------------------------------------------------------------
// Scratch (device globals)
// ---------------------------------------------------------------------------
__device__ float g_qkv[MM*3*CC];   // fused self-attn q|k|v, row stride 3072
__device__ float g_kv [MM*2*CC];   // fused cross-attn k|v, row stride 2048
__device__ float g_q  [MM*CC];     // cross-attn q
__device__ float g_x1 [MM*CC];
__device__ float g_x2 [MM*CC];
__device__ __half g_af [MM*CC];    // fp16 activations (GEMM A operand)
__device__ __half g_ff [MM*FF];    // fp16 FFN intermediate
__device__ __half g_wt [CC*FF];    // fp16 transposed weights (max 4M elems)

// ---------------------------------------------------------------------------
// LayerNorm emitting fp16
// ---------------------------------------------------------------------------
__global__ __launch_bounds__(256)
void ln_h_kernel(const float* __restrict__ x, const float* __restrict__ gamma,
                 const float* __restrict__ beta, __half* __restrict__ oh)
{
    __shared__ float red[8];
    const int row = blockIdx.x;
    const int t = threadIdx.x;
    const float4 v = ((const float4*)(x + (size_t)row * CC))[t];

    float s = v.x + v.y + v.z + v.w;
    #pragma unroll
    for (int o = 16; o; o >>= 1) s += __shfl_xor_sync(0xffffffffu, s, o);
    if ((t & 31) == 0) red[t >> 5] = s;
    __syncthreads();
    float tot = 0.f;
    #pragma unroll
    for (int i = 0; i < 8; i++) tot += red[i];
    const float mu = tot * (1.0f / CC);
    __syncthreads();

    const float dx = v.x - mu, dy = v.y - mu, dz = v.z - mu, dw = v.w - mu;
    float s2 = dx*dx + dy*dy + dz*dz + dw*dw;
    #pragma unroll
    for (int o = 16; o; o >>= 1) s2 += __shfl_xor_sync(0xffffffffu, s2, o);
    if ((t & 31) == 0) red[t >> 5] = s2;
    __syncthreads();
    float tot2 = 0.f;
    #pragma unroll
    for (int i = 0; i < 8; i++) tot2 += red[i];
    const float inv = rsqrtf(tot2 * (1.0f / CC) + 1e-5f);

    const float4 g4 = ((const float4*)gamma)[t];
    const float4 b4 = ((const float4*)beta)[t];
    uint2 hh;
    hh.x = pack_h2(dx * inv * g4.x + b4.x, dy * inv * g4.y + b4.y);
    hh.y = pack_h2(dz * inv * g4.z + b4.z, dw * inv * g4.w + b4.w);
    ((uint2*)(oh + (size_t)row * CC))[t] = hh;
}

// ---------------------------------------------------------------------------
// Elementwise fp32 -> fp16 (for enc)
// ---------------------------------------------------------------------------
__global__ __launch_bounds__(256)
void convert_h_kernel(const float* __restrict__ in, __half* __restrict__ oh, int n4)
{
    const int i = blockIdx.x * 256 + threadIdx.x;
    if (i >= n4) return;
    const float4 v = ((const float4*)in)[i];
    uint2 hh;
    hh.x = pack_h2(v.x, v.y);
    hh.y = pack_h2(v.z, v.w);
    ((uint2*)oh)[i] = hh;
}

// ---------------------------------------------------------------------------
// Weight transpose: W[K,N] fp32 -> Wt[N,K] fp16
// ---------------------------------------------------------------------------
__global__ __launch_bounds__(256)
void wtrans_h_kernel(const float* __restrict__ W, __half* __restrict__ th,
                     int K, int N)
{
    __shared__ float tile[32][33];
    const int bx = blockIdx.x;
    const int by = blockIdx.y;
    const int tx = threadIdx.x & 31;
    const int ty = threadIdx.x >> 5;
    #pragma unroll
    for (int i = 0; i < 32; i += 8)
        tile[ty + i][tx] = W[(size_t)(by*32 + ty + i) * N + bx*32 + tx];
    __syncthreads();
    #pragma unroll
    for (int i = 0; i < 32; i += 8) {
        const size_t o = (size_t)(bx*32 + ty + i) * K + by*32 + tx;
        th[o] = __float2half_rn(tile[tx][ty + i]);
    }
}

// ---------------------------------------------------------------------------
// HMMA GEMM (fp16 single precision path): D[M,N] = A[M,K] @ Wt[N,K]^T.
// 128x128 CTA tile, 16 warps (4 M x 4 N), warp tile 32x32, m16n8k16.
// 4-stage cp.async pipeline, one __syncthreads per k32-chunk.
// ---------------------------------------------------------------------------
#define ROWB 80                            // padded row stride bytes (32 fp16 data)
#define TILE_B (128 * ROWB)                // 10240
#define STAGE_B (2 * TILE_B)               // A, B = 20480
#define NSTAGE 4
#define MMA_SMEM (NSTAGE * STAGE_B)        // 81920

template <bool RELU, bool HALFOUT>
__global__ __launch_bounds__(512, 1)
void mma_gemm_kernel(const __half* __restrict__ A,
                     const __half* __restrict__ B,
                     float* __restrict__ C,
                     __half* __restrict__ Ch,
                     int N, int K,
                     const float* __restrict__ bias,
                     const float* __restrict__ residual)
{
    extern __shared__ char dsm[];
    const uint32_t sbase = smem_u32(dsm);

    const int tid = threadIdx.x;
    const int wid = tid >> 5;
    const int lane = tid & 31;
    const int bx = blockIdx.x, by = blockIdx.y;
    const int wm = wid & 3;          // 0..3 (M)
    const int wn = wid >> 2;         // 0..3 (N)

    const int lrow = tid >> 2;       // 0..127
    const int lq   = tid & 3;        // 16B quarter of the 64B row chunk
    const char* srcA = (const char*)(A + (size_t)(by*128 + lrow) * K);
    const char* srcB = (const char*)(B + (size_t)(bx*128 + lrow) * K);
    const uint32_t dst_row = lrow * ROWB + lq * 16;

    const int nck = K >> 5;          // 32 fp16 per chunk

    auto load_stage = [&](int stage, int i) {
        const size_t go = (size_t)i * 64 + lq * 16;
        const uint32_t d = sbase + stage * STAGE_B + dst_row;
        cp16(d + 0*TILE_B, srcA + go);
        cp16(d + 1*TILE_B, srcB + go);
        cp_commit();
    };

    float acc[2][4][4];
    #pragma unroll
    for (int mt = 0; mt < 2; mt++)
        #pragma unroll
        for (int nt = 0; nt < 4; nt++)
            #pragma unroll
            for (int e = 0; e < 4; e++) acc[mt][nt][e] = 0.f;

    load_stage(0, 0);
    load_stage(1, 1);
    load_stage(2, 2);

    const uint32_t aoff = (wm*32 + (lane & 15)) * ROWB + ((lane >> 4) & 1) * 16;
    const uint32_t boff = (wn*32 + (lane & 7) + ((lane >> 4) & 1) * 8) * ROWB
                        + ((lane >> 3) & 1) * 16;

    for (int i = 0; i < nck; i++) {
        cp_wait<2>();
        __syncthreads();

        const uint32_t base = sbase + (i % NSTAGE) * STAGE_B;
        #pragma unroll
        for (int kk = 0; kk < 2; kk++) {
            const uint32_t kb = kk * 32;
            uint32_t ah[2][4];
            #pragma unroll
            for (int mt = 0; mt < 2; mt++)
                ldsm4(ah[mt], base + 0*TILE_B + aoff + mt * 16 * ROWB + kb);
            uint32_t bh[8];
            #pragma unroll
            for (int nt2 = 0; nt2 < 2; nt2++)
                ldsm4(bh + nt2*4, base + 1*TILE_B + boff + nt2 * 16 * ROWB + kb);
            #pragma unroll
            for (int mt = 0; mt < 2; mt++)
                #pragma unroll
                for (int nt = 0; nt < 4; nt++)
                    mma16816(acc[mt][nt], ah[mt], bh + nt*2);
        }

        if (i + 3 < nck) load_stage((i + 3) % NSTAGE, i + 3);
    }

    // ---- epilogue ----
    const int r0 = by*128 + wm*32;
    const int c0 = bx*128 + wn*32;
    #pragma unroll
    for (int mt = 0; mt < 2; mt++) {
        #pragma unroll
        for (int nt = 0; nt < 4; nt++) {
            const int r = r0 + mt*16 + (lane >> 2);
            const int c = c0 + nt*8 + (lane & 3) * 2;
            #pragma unroll
            for (int half = 0; half < 2; half++) {
                const int rr = r + half * 8;
                float v0 = acc[mt][nt][half*2 + 0];
                float v1 = acc[mt][nt][half*2 + 1];
                if (bias) { v0 += bias[c]; v1 += bias[c + 1]; }
                if (RELU) { v0 = fmaxf(v0, 0.f); v1 = fmaxf(v1, 0.f); }
                if (HALFOUT) {
                    *(unsigned*)(Ch + (size_t)rr * N + c) = pack_h2(v0, v1);
                } else {
                    if (residual) {
                        const float2 rv = *(const float2*)&residual[(size_t)rr * N + c];
                        v0 += rv.x; v1 += rv.y;
                    }
                    *(float2*)&C[(size_t)rr * N + c] = make_float2(v0, v1);
                }
            }
        }
    }
}

// ---------------------------------------------------------------------------
// Flash attention fp32, 4x4 micro-tile + f32x2. Runtime row strides so Q/K/V
// can live in fused projection outputs. Output: fp16 (stride CC).
// ---------------------------------------------------------------------------
#define AL 68
#define ATT_SMEM_BYTES (4 * 64 * AL * (int)sizeof(float))   // 69632

template <bool CAUSAL>
__global__ __launch_bounds__(256)
void attn_kernel(const float* __restrict__ Q, const float* __restrict__ K,
                 const float* __restrict__ V, int sQ, int sKV,
                 __half* __restrict__ Oh)
{
    extern __shared__ float sm[];
    float* Qs = sm;
    float* Ks = Qs + 64*AL;
    float* Vs = Ks + 64*AL;
    float* Pt = Vs + 64*AL;   // [key][query]

    const int qt = blockIdx.x, h = blockIdx.y, b = blockIdx.z;
    const int tid = threadIdx.x;
    const int tr = tid >> 4, tc = tid & 15;
    const int qr = tr * 4;
    const int dc = tc * 4;

    const size_t qrow0 = (size_t)b*TT + qt*64;

    {
        const int r = tid >> 2, c0 = (tid & 3) * 16;
        const float4* src = (const float4*)(Q + (qrow0 + r) * sQ + h*DD + c0);
        float4* dst = (float4*)(Qs + r*AL + c0);
        dst[0] = src[0]; dst[1] = src[1]; dst[2] = src[2]; dst[3] = src[3];
    }

    ull o2[2][4];
    {
        const ull z = pack2(0.f, 0.f);
        #pragma unroll
        for (int i = 0; i < 2; i++)
            #pragma unroll
            for (int j = 0; j < 4; j++) o2[i][j] = z;
    }
    float m[4], l[4];
    #pragma unroll
    for (int i = 0; i < 4; i++) { m[i] = -CUDART_INF_F; l[i] = 0.f; }

    const int nkt = CAUSAL ? (qt + 1) : (TT / 64);

    for (int kt = 0; kt < nkt; kt++) {
        __syncthreads();
        {
            const size_t krow0 = (size_t)b*TT + kt*64;
            const int r = tid >> 2, c0 = (tid & 3) * 16;
            const float4* ks = (const float4*)(K + (krow0 + r) * sKV + h*DD + c0);
            const float4* vs = (const float4*)(V + (krow0 + r) * sKV + h*DD + c0);
            float4* kd = (float4*)(Ks + r*AL + c0);
            float4* vd = (float4*)(Vs + r*AL + c0);
            #pragma unroll
            for (int i = 0; i < 4; i++) { kd[i] = ks[i]; vd[i] = vs[i]; }
        }
        __syncthreads();

        ull s2[4][4];
        {
            const ull z = pack2(0.f, 0.f);
            #pragma unroll
            for (int i = 0; i < 4; i++)
                #pragma unroll
                for (int j = 0; j < 4; j++) s2[i][j] = z;
        }
        #pragma unroll
        for (int d = 0; d < DD; d += 4) {
            const ulonglong2 q0 = *(const ulonglong2*)&Qs[(qr+0)*AL + d];
            const ulonglong2 q1 = *(const ulonglong2*)&Qs[(qr+1)*AL + d];
            const ulonglong2 q2 = *(const ulonglong2*)&Qs[(qr+2)*AL + d];
            const ulonglong2 q3 = *(const ulonglong2*)&Qs[(qr+3)*AL + d];
            const ulonglong2 k0 = *(const ulonglong2*)&Ks[(tc +  0)*AL + d];
            const ulonglong2 k1 = *(const ulonglong2*)&Ks[(tc + 16)*AL + d];
            const ulonglong2 k2 = *(const ulonglong2*)&Ks[(tc + 32)*AL + d];
            const ulonglong2 k3 = *(const ulonglong2*)&Ks[(tc + 48)*AL + d];
            fma2(s2[0][0], q0.x, k0.x); fma2(s2[0][0], q0.y, k0.y);
            fma2(s2[0][1], q0.x, k1.x); fma2(s2[0][1], q0.y, k1.y);
            fma2(s2[0][2], q0.x, k2.x); fma2(s2[0][2], q0.y, k2.y);
            fma2(s2[0][3], q0.x, k3.x); fma2(s2[0][3], q0.y, k3.y);
            fma2(s2[1][0], q1.x, k0.x); fma2(s2[1][0], q1.y, k0.y);
            fma2(s2[1][1], q1.x, k1.x); fma2(s2[1][1], q1.y, k1.y);
            fma2(s2[1][2], q1.x, k2.x); fma2(s2[1][2], q1.y, k2.y);
            fma2(s2[1][3], q1.x, k3.x); fma2(s2[1][3], q1.y, k3.y);
            fma2(s2[2][0], q2.x, k0.x); fma2(s2[2][0], q2.y, k0.y);
            fma2(s2[2][1], q2.x, k1.x); fma2(s2[2][1], q2.y, k1.y);
            fma2(s2[2][2], q2.x, k2.x); fma2(s2[2][2], q2.y, k2.y);
            fma2(s2[2][3], q2.x, k3.x); fma2(s2[2][3], q2.y, k3.y);
            fma2(s2[3][0], q3.x, k0.x); fma2(s2[3][0], q3.y, k0.y);
            fma2(s2[3][1], q3.x, k1.x); fma2(s2[3][1], q3.y, k1.y);
            fma2(s2[3][2], q3.x, k2.x); fma2(s2[3][2], q3.y, k2.y);
            fma2(s2[3][3], q3.x, k3.x); fma2(s2[3][3], q3.y, k3.y);
        }

        float s[4][4];
        #pragma unroll
        for (int i = 0; i < 4; i++)
            #pragma unroll
            for (int j = 0; j < 4; j++) {
                const float2 t = unpack2(s2[i][j]);
                s[i][j] = (t.x + t.y) * 0.125f;
            }

        if (CAUSAL && kt == qt) {
            #pragma unroll
            for (int i = 0; i < 4; i++)
                #pragma unroll
                for (int j = 0; j < 4; j++)
                    if (tc + 16*j > qr + i) s[i][j] = -CUDART_INF_F;
        }

        float corr[4];
        #pragma unroll
        for (int i = 0; i < 4; i++) {
            float mloc = fmaxf(fmaxf(s[i][0], s[i][1]), fmaxf(s[i][2], s[i][3]));
            #pragma unroll
            for (int o = 8; o; o >>= 1)
                mloc = fmaxf(mloc, __shfl_xor_sync(0xffffffffu, mloc, o));
            const float mn = fmaxf(m[i], mloc);
            corr[i] = __expf(m[i] - mn);
            m[i] = mn;
            float lsum = 0.f;
            #pragma unroll
            for (int j = 0; j < 4; j++) {
                const float p = __expf(s[i][j] - mn);
                s[i][j] = p;
                lsum += p;
            }
            #pragma unroll
            for (int o = 8; o; o >>= 1)
                lsum += __shfl_xor_sync(0xffffffffu, lsum, o);
            l[i] = l[i] * corr[i] + lsum;
        }

        {
            const ull c01 = pack2(corr[0], corr[1]);
            const ull c23 = pack2(corr[2], corr[3]);
            #pragma unroll
            for (int dj = 0; dj < 4; dj++) { mul2(o2[0][dj], c01); mul2(o2[1][dj], c23); }
        }

        #pragma unroll
        for (int j = 0; j < 4; j++)
            *(float4*)&Pt[(tc + 16*j)*AL + qr] =
                make_float4(s[0][j], s[1][j], s[2][j], s[3][j]);
        __syncwarp();
        __syncthreads();

        #pragma unroll 4
        for (int kj = 0; kj < 64; kj++) {
            const ulonglong2 p2 = *(const ulonglong2*)&Pt[kj*AL + qr];
            const float4 v = *(const float4*)&Vs[kj*AL + dc];
            const ull vx = pack2(v.x, v.x);
            const ull vy = pack2(v.y, v.y);
            const ull vz = pack2(v.z, v.z);
            const ull vw = pack2(v.w, v.w);
            fma2(o2[0][0], p2.x, vx); fma2(o2[0][1], p2.x, vy);
            fma2(o2[0][2], p2.x, vz); fma2(o2[0][3], p2.x, vw);
            fma2(o2[1][0], p2.y, vx); fma2(o2[1][1], p2.y, vy);
            fma2(o2[1][2], p2.y, vz); fma2(o2[1][3], p2.y, vw);
        }
    }

    float inv[4];
    #pragma unroll
    for (int i = 0; i < 4; i++) inv[i] = 1.f / l[i];

    float oo[4][4];
    #pragma unroll
    for (int dj = 0; dj < 4; dj++) {
        const float2 t0 = unpack2(o2[0][dj]);
        const float2 t1 = unpack2(o2[1][dj]);
        oo[0][dj] = t0.x * inv[0];
        oo[1][dj] = t0.y * inv[1];
        oo[2][dj] = t1.x * inv[2];
        oo[3][dj] = t1.y * inv[3];
    }
    #pragma unroll
    for (int i = 0; i < 4; i++) {
        uint2 hh;
        hh.x = pack_h2(oo[i][0], oo[i][1]);
        hh.y = pack_h2(oo[i][2], oo[i][3]);
        const size_t off = (qrow0 + qr + i) * CC + h*DD + dc;
        *(uint2*)(Oh + off) = hh;
    }
}

// ---------------------------------------------------------------------------
// Host launcher
// ---------------------------------------------------------------------------
extern "C" void kernel_launch(void* const* d_in, const int* in_sizes, int n_in,
                              void* d_out, int out_size)
{
    (void)in_sizes; (void)n_in; (void)out_size;
    const float* x      = (const float*)d_in[0];
    const float* enc    = (const float*)d_in[1];
    const float* sa_wq  = (const float*)d_in[2];
    const float* sa_wk  = (const float*)d_in[3];
    const float* sa_wv  = (const float*)d_in[4];
    const float* sa_wo  = (const float*)d_in[5];
    const float* sa_bo  = (const float*)d_in[6];
    const float* ca_wq  = (const float*)d_in[7];
    const float* ca_wk  = (const float*)d_in[8];
    const float* ca_wv  = (const float*)d_in[9];
    const float* ca_wo  = (const float*)d_in[10];
    const float* ca_bo  = (const float*)d_in[11];
    const float* ff_w1  = (const float*)d_in[12];
    const float* ff_b1  = (const float*)d_in[13];
    const float* ff_w2  = (const float*)d_in[14];
    const float* ff_b2  = (const float*)d_in[15];
    const float* ln1_g  = (const float*)d_in[16];
    const float* ln1_b  = (const float*)d_in[17];
    const float* ln2_g  = (const float*)d_in[18];
    const float* ln2_b  = (const float*)d_in[19];
    const float* ln3_g  = (const float*)d_in[20];
    const float* ln3_b  = (const float*)d_in[21];
    float* out = (float*)d_out;

    float *qkv, *kv, *q, *x1, *x2;
    __half *af, *ff16, *wt;
    cudaGetSymbolAddress((void**)&qkv, g_qkv);
    cudaGetSymbolAddress((void**)&kv,  g_kv);
    cudaGetSymbolAddress((void**)&q,   g_q);
    cudaGetSymbolAddress((void**)&x1,  g_x1);
    cudaGetSymbolAddress((void**)&x2,  g_x2);
    cudaGetSymbolAddress((void**)&af,  g_af);
    cudaGetSymbolAddress((void**)&ff16,g_ff);
    cudaGetSymbolAddress((void**)&wt,  g_wt);

    cudaFuncSetAttribute(attn_kernel<true>,
                         cudaFuncAttributeMaxDynamicSharedMemorySize, ATT_SMEM_BYTES);
    cudaFuncSetAttribute(attn_kernel<false>,
                         cudaFuncAttributeMaxDynamicSharedMemorySize, ATT_SMEM_BYTES);
    cudaFuncSetAttribute(mma_gemm_kernel<false, false>,
                         cudaFuncAttributeMaxDynamicSharedMemorySize, MMA_SMEM);
    cudaFuncSetAttribute(mma_gemm_kernel<true, true>,
                         cudaFuncAttributeMaxDynamicSharedMemorySize, MMA_SMEM);

    const dim3 gAttn(TT/64, HH, BB);
    const dim3 gT1(CC/32, CC/32);
    const dim3 gT2(FF/32, CC/32);
    const dim3 gT3(CC/32, FF/32);
    const int cvt_blocks = (MM*CC/4 + 255) / 256;

    #define GEMM(N_, K_, BIAS, RES, OUT) \
        mma_gemm_kernel<false,false><<<dim3((N_)/128, MM/128), 512, MMA_SMEM>>>( \
            af, wt, OUT, nullptr, N_, K_, BIAS, RES)

    // ---- self-attention ----
    ln_h_kernel<<<MM, 256>>>(x, ln1_g, ln1_b, af);
    wtrans_h_kernel<<<gT1, 256>>>(sa_wq, wt + 0*CC*CC, CC, CC);
    wtrans_h_kernel<<<gT1, 256>>>(sa_wk, wt + 1*CC*CC, CC, CC);
    wtrans_h_kernel<<<gT1, 256>>>(sa_wv, wt + 2*CC*CC, CC, CC);
    GEMM(3*CC, CC, nullptr, nullptr, qkv);                    // fused q|k|v
    attn_kernel<true><<<gAttn, 256, ATT_SMEM_BYTES>>>(
        qkv, qkv + CC, qkv + 2*CC, 3*CC, 3*CC, af);
    wtrans_h_kernel<<<gT1, 256>>>(sa_wo, wt, CC, CC);
    GEMM(CC, CC, sa_bo, x, x1);

    // ---- cross-attention ----
    ln_h_kernel<<<MM, 256>>>(x1, ln2_g, ln2_b, af);
    wtrans_h_kernel<<<gT1, 256>>>(ca_wq, wt, CC, CC);
    GEMM(CC, CC, nullptr, nullptr, q);
    convert_h_kernel<<<cvt_blocks, 256>>>(enc, af, MM*CC/4);
    wtrans_h_kernel<<<gT1, 256>>>(ca_wk, wt + 0*CC*CC, CC, CC);
    wtrans_h_kernel<<<gT1, 256>>>(ca_wv, wt + 1*CC*CC, CC, CC);
    GEMM(2*CC, CC, nullptr, nullptr, kv);                     // fused k|v
    attn_kernel<false><<<gAttn, 256, ATT_SMEM_BYTES>>>(
        q, kv, kv + CC, CC, 2*CC, af);
    wtrans_h_kernel<<<gT1, 256>>>(ca_wo, wt, CC, CC);
    GEMM(CC, CC, ca_bo, x1, x2);

    // ---- FFN ----
    ln_h_kernel<<<MM, 256>>>(x2, ln3_g, ln3_b, af);
    wtrans_h_kernel<<<gT2, 256>>>(ff_w1, wt, CC, FF);
    mma_gemm_kernel<true, true><<<dim3(FF/128, MM/128), 512, MMA_SMEM>>>(
        af, wt, nullptr, ff16, FF, CC, ff_b1, nullptr);
    wtrans_h_kernel<<<gT3, 256>>>(ff_w2, wt, FF, CC);
    mma_gemm_kernel<false, false><<<dim3(CC/128, MM/128), 512, MMA_SMEM>>>(
        ff16, wt, out, nullptr, CC, FF, ff_b2, x2);

    #undef GEMM
}